// round 1
// baseline (speedup 1.0000x reference)
#include <cuda_runtime.h>

#define B_  2
#define S_  2048
#define D_  1024
#define H_  16
#define HD_ 64
#define M_  (B_*S_)   // 4096

// Scratch (device globals: no allocations allowed)
__device__ float g_Q[M_*D_];
__device__ float g_K[M_*D_];
__device__ float g_V[M_*D_];
__device__ float g_Y[M_*D_];

// ---------------------------------------------------------------------------
// SGEMM NT with bias: C[M,N] = A[M,K] @ W[N,K]^T + bias[N]
// M=4096, N=K=1024. 128x128x8 tile, 8x8 per thread, 256 threads.
// ---------------------------------------------------------------------------
__global__ __launch_bounds__(256, 2)
void sgemm_nt_bias(const float* __restrict__ A, const float* __restrict__ W,
                   const float* __restrict__ bias, float* __restrict__ C)
{
    const int K = D_, N = D_;
    __shared__ float AT[8][128];
    __shared__ float BT[8][128];

    const int tid = threadIdx.x;
    const int tx  = tid & 15;
    const int ty  = tid >> 4;
    const int bn  = blockIdx.x * 128;
    const int bm  = blockIdx.y * 128;

    // loader mapping: each thread loads one float4 of A and of W per k-step
    const int lr = tid >> 1;          // 0..127 (tile row)
    const int lc = (tid & 1) * 4;     // 0 or 4 (k offset)
    const float* Ap = A + (size_t)(bm + lr) * K + lc;
    const float* Wp = W + (size_t)(bn + lr) * K + lc;

    float acc[8][8];
#pragma unroll
    for (int i = 0; i < 8; i++)
#pragma unroll
        for (int j = 0; j < 8; j++) acc[i][j] = 0.0f;

    for (int kt = 0; kt < K; kt += 8) {
        float4 av = *(const float4*)(Ap + kt);
        float4 wv = *(const float4*)(Wp + kt);
        __syncthreads();
        AT[lc+0][lr] = av.x; AT[lc+1][lr] = av.y;
        AT[lc+2][lr] = av.z; AT[lc+3][lr] = av.w;
        BT[lc+0][lr] = wv.x; BT[lc+1][lr] = wv.y;
        BT[lc+2][lr] = wv.z; BT[lc+3][lr] = wv.w;
        __syncthreads();
#pragma unroll
        for (int kk = 0; kk < 8; kk++) {
            float4 a0 = *(const float4*)&AT[kk][ty*8];
            float4 a1 = *(const float4*)&AT[kk][ty*8+4];
            float4 b0 = *(const float4*)&BT[kk][tx*8];
            float4 b1 = *(const float4*)&BT[kk][tx*8+4];
            float ar[8] = {a0.x,a0.y,a0.z,a0.w,a1.x,a1.y,a1.z,a1.w};
            float br[8] = {b0.x,b0.y,b0.z,b0.w,b1.x,b1.y,b1.z,b1.w};
#pragma unroll
            for (int i = 0; i < 8; i++)
#pragma unroll
                for (int j = 0; j < 8; j++)
                    acc[i][j] += ar[i] * br[j];
        }
    }

    const int row0 = bm + ty * 8;
    const int col0 = bn + tx * 8;
    float bs[8];
#pragma unroll
    for (int j = 0; j < 8; j++) bs[j] = bias[col0 + j];
#pragma unroll
    for (int i = 0; i < 8; i++) {
        float4 v0 = make_float4(acc[i][0]+bs[0], acc[i][1]+bs[1],
                                acc[i][2]+bs[2], acc[i][3]+bs[3]);
        float4 v1 = make_float4(acc[i][4]+bs[4], acc[i][5]+bs[5],
                                acc[i][6]+bs[6], acc[i][7]+bs[7]);
        *(float4*)&C[(size_t)(row0+i)*N + col0]     = v0;
        *(float4*)&C[(size_t)(row0+i)*N + col0 + 4] = v1;
    }
}

// ---------------------------------------------------------------------------
// Flash-attention (fp32, online softmax).
// Block = 256 threads (16x16), handles 64 queries of one (b, h).
// Shared: Qs [q][d] (natural), Ks XOR-swizzled [d][k] (reused as P^T [k][q]),
//         Vs [k][d] (natural). Exactly 48 KB static smem.
// ---------------------------------------------------------------------------
__device__ __forceinline__ int swz(int r, int c) { return r * 64 + (c ^ (r & 31)); }

__global__ __launch_bounds__(256, 2)
void attn_kernel(const float* __restrict__ Q, const float* __restrict__ Kg,
                 const float* __restrict__ Vg, float* __restrict__ Y)
{
    __shared__ float Qs[64*64];
    __shared__ float Ks[64*64];  // swizzled; holds K^T then P^T
    __shared__ float Vs[64*64];

    const int tid = threadIdx.x;
    const int tx  = tid & 15;
    const int ty  = tid >> 4;
    const int q0  = blockIdx.x * 64;
    const int bh  = blockIdx.y;
    const int b   = bh >> 4;
    const int h   = bh & 15;

    const float* Qp = Q  + (size_t)b * S_ * D_ + (size_t)h * HD_;
    const float* Kp = Kg + (size_t)b * S_ * D_ + (size_t)h * HD_;
    const float* Vp = Vg + (size_t)b * S_ * D_ + (size_t)h * HD_;

    // Load 64x64 Q tile (coalesced, conflict-free writes)
    for (int idx = tid; idx < 64*64; idx += 256) {
        int r = idx >> 6, d = idx & 63;
        Qs[r * 64 + d] = Qp[(size_t)(q0 + r) * D_ + d];
    }

    float m_i[4], l_i[4], O[4][4];
#pragma unroll
    for (int i = 0; i < 4; i++) {
        m_i[i] = -1e30f; l_i[i] = 0.0f;
#pragma unroll
        for (int j = 0; j < 4; j++) O[i][j] = 0.0f;
    }
    __syncthreads();

    for (int k0 = 0; k0 < S_; k0 += 64) {
        // Load K (transposed+swizzled) and V tiles
        for (int idx = tid; idx < 64*64; idx += 256) {
            int key = idx >> 6, d = idx & 63;
            Ks[swz(d, key)]   = Kp[(size_t)(k0 + key) * D_ + d];
            Vs[key * 64 + d]  = Vp[(size_t)(k0 + key) * D_ + d];
        }
        __syncthreads();

        // S = Q K^T (64x64x64), 4x4 micro-tile
        float s[4][4];
#pragma unroll
        for (int i = 0; i < 4; i++)
#pragma unroll
            for (int j = 0; j < 4; j++) s[i][j] = 0.0f;

#pragma unroll 8
        for (int kk = 0; kk < 64; kk++) {
            float a[4], bb[4];
#pragma unroll
            for (int i = 0; i < 4; i++) a[i]  = Qs[(ty*4 + i) * 64 + kk];
#pragma unroll
            for (int j = 0; j < 4; j++) bb[j] = Ks[swz(kk, tx*4 + j)];
#pragma unroll
            for (int i = 0; i < 4; i++)
#pragma unroll
                for (int j = 0; j < 4; j++)
                    s[i][j] += a[i] * bb[j];
        }

        // Online softmax update (row reductions across the 16-lane tx group)
#pragma unroll
        for (int i = 0; i < 4; i++) {
#pragma unroll
            for (int j = 0; j < 4; j++) s[i][j] *= 0.125f;  // 1/sqrt(64)
            float rm = fmaxf(fmaxf(s[i][0], s[i][1]), fmaxf(s[i][2], s[i][3]));
#pragma unroll
            for (int off = 1; off < 16; off <<= 1)
                rm = fmaxf(rm, __shfl_xor_sync(0xffffffffu, rm, off, 16));
            float mn    = fmaxf(m_i[i], rm);
            float alpha = __expf(m_i[i] - mn);
            float rs = 0.0f;
#pragma unroll
            for (int j = 0; j < 4; j++) {
                s[i][j] = __expf(s[i][j] - mn);
                rs += s[i][j];
            }
#pragma unroll
            for (int off = 1; off < 16; off <<= 1)
                rs += __shfl_xor_sync(0xffffffffu, rs, off, 16);
            l_i[i] = l_i[i] * alpha + rs;
#pragma unroll
            for (int j = 0; j < 4; j++) O[i][j] *= alpha;
            m_i[i] = mn;
        }

        __syncthreads();  // everyone done reading Ks (K^T)
        // Write P^T into the Ks buffer: P^T[k][q]
#pragma unroll
        for (int j = 0; j < 4; j++)
#pragma unroll
            for (int i = 0; i < 4; i++)
                Ks[swz(tx*4 + j, ty*4 + i)] = s[i][j];
        __syncthreads();

        // O += P V (64x64x64): rows = queries (ty), cols = dims (tx)
#pragma unroll 8
        for (int kk = 0; kk < 64; kk++) {
            float a[4], bb[4];
#pragma unroll
            for (int i = 0; i < 4; i++) a[i]  = Ks[swz(kk, ty*4 + i)];
#pragma unroll
            for (int j = 0; j < 4; j++) bb[j] = Vs[kk * 64 + tx*4 + j];
#pragma unroll
            for (int i = 0; i < 4; i++)
#pragma unroll
                for (int j = 0; j < 4; j++)
                    O[i][j] += a[i] * bb[j];
        }
        __syncthreads();  // before next tile overwrites Ks/Vs
    }

    // Epilogue: normalize and write Y[b, s, h*64 + d] (vectorized)
#pragma unroll
    for (int i = 0; i < 4; i++) {
        float inv = 1.0f / l_i[i];
        float4 o = make_float4(O[i][0]*inv, O[i][1]*inv, O[i][2]*inv, O[i][3]*inv);
        *(float4*)&Y[(size_t)(b * S_ + q0 + ty*4 + i) * D_ + h * HD_ + tx*4] = o;
    }
}

// ---------------------------------------------------------------------------
// Launch
// ---------------------------------------------------------------------------
extern "C" void kernel_launch(void* const* d_in, const int* in_sizes, int n_in,
                              void* d_out, int out_size)
{
    const float* dec = (const float*)d_in[0];
    const float* enc = (const float*)d_in[1];
    const float* Wq  = (const float*)d_in[2];
    const float* bq  = (const float*)d_in[3];
    const float* Wk  = (const float*)d_in[4];
    const float* bk  = (const float*)d_in[5];
    const float* Wv  = (const float*)d_in[6];
    const float* bv  = (const float*)d_in[7];
    const float* Wp  = (const float*)d_in[8];
    const float* bp  = (const float*)d_in[9];
    float* out = (float*)d_out;

    float *Qd, *Kd, *Vd, *Yd;
    cudaGetSymbolAddress((void**)&Qd, g_Q);
    cudaGetSymbolAddress((void**)&Kd, g_K);
    cudaGetSymbolAddress((void**)&Vd, g_V);
    cudaGetSymbolAddress((void**)&Yd, g_Y);

    dim3 ggrid(D_ / 128, M_ / 128);   // (8, 32)

    sgemm_nt_bias<<<ggrid, 256>>>(dec, Wq, bq, Qd);
    sgemm_nt_bias<<<ggrid, 256>>>(enc, Wk, bk, Kd);
    sgemm_nt_bias<<<ggrid, 256>>>(enc, Wv, bv, Vd);
    attn_kernel<<<dim3(S_ / 64, B_ * H_), 256>>>(Qd, Kd, Vd, Yd);
    sgemm_nt_bias<<<ggrid, 256>>>(Yd, Wp, bp, out);
}

// round 3
// speedup vs baseline: 1.2700x; 1.2700x over previous
#include <cuda_runtime.h>
#include <cuda_bf16.h>
#include <cstdint>

#define B_  2
#define S_  2048
#define D_  1024
#define H_  16
#define HD_ 64
#define M_  (B_*S_)   // 4096

// ---------------------------------------------------------------------------
// Scratch (device globals: no allocations allowed)
// ---------------------------------------------------------------------------
__device__ float g_Q[M_*D_];
__device__ float g_K[M_*D_];
__device__ float g_V[M_*D_];
__device__ float g_Y[M_*D_];

__device__ __nv_bfloat16 g_decH[M_*D_], g_decL[M_*D_];
__device__ __nv_bfloat16 g_encH[M_*D_], g_encL[M_*D_];
__device__ __nv_bfloat16 g_yH[M_*D_],   g_yL[M_*D_];
__device__ __nv_bfloat16 g_wqH[D_*D_],  g_wqL[D_*D_];
__device__ __nv_bfloat16 g_wkH[D_*D_],  g_wkL[D_*D_];
__device__ __nv_bfloat16 g_wvH[D_*D_],  g_wvL[D_*D_];
__device__ __nv_bfloat16 g_wpH[D_*D_],  g_wpL[D_*D_];

// ---------------------------------------------------------------------------
// fp32 -> (hi, lo) bf16 split
// ---------------------------------------------------------------------------
__global__ __launch_bounds__(256)
void split_bf16(const float* __restrict__ src,
                __nv_bfloat16* __restrict__ hi,
                __nv_bfloat16* __restrict__ lo, int n4)
{
    int i = blockIdx.x * blockDim.x + threadIdx.x;
    if (i >= n4) return;
    float4 v = ((const float4*)src)[i];
    float x[4] = {v.x, v.y, v.z, v.w};
    unsigned short h[4], l[4];
#pragma unroll
    for (int j = 0; j < 4; j++) {
        __nv_bfloat16 hb = __float2bfloat16(x[j]);
        __nv_bfloat16 lb = __float2bfloat16(x[j] - __bfloat162float(hb));
        h[j] = __bfloat16_as_ushort(hb);
        l[j] = __bfloat16_as_ushort(lb);
    }
    uint2 hv, lv;
    hv.x = (uint32_t)h[0] | ((uint32_t)h[1] << 16);
    hv.y = (uint32_t)h[2] | ((uint32_t)h[3] << 16);
    lv.x = (uint32_t)l[0] | ((uint32_t)l[1] << 16);
    lv.y = (uint32_t)l[2] | ((uint32_t)l[3] << 16);
    ((uint2*)hi)[i] = hv;
    ((uint2*)lo)[i] = lv;
}

// ---------------------------------------------------------------------------
// HMMA helpers (baseline PTX; no sm_103a-gated features)
// ---------------------------------------------------------------------------
__device__ __forceinline__ uint32_t smem_u32(const void* p) {
    uint32_t a;
    asm("{ .reg .u64 t; cvta.to.shared.u64 t, %1; cvt.u32.u64 %0, t; }"
        : "=r"(a) : "l"(p));
    return a;
}

__device__ __forceinline__ void mma16816(float* c, const uint32_t* a, const uint32_t* b) {
    asm volatile(
        "mma.sync.aligned.m16n8k16.row.col.f32.bf16.bf16.f32 "
        "{%0,%1,%2,%3}, {%4,%5,%6,%7}, {%8,%9}, {%0,%1,%2,%3};"
        : "+f"(c[0]), "+f"(c[1]), "+f"(c[2]), "+f"(c[3])
        : "r"(a[0]), "r"(a[1]), "r"(a[2]), "r"(a[3]), "r"(b[0]), "r"(b[1]));
}

__device__ __forceinline__ void cp_async16(uint32_t dst, const void* src) {
    asm volatile("cp.async.cg.shared.global [%0], [%1], 16;\n"
                 :: "r"(dst), "l"(src) : "memory");
}
__device__ __forceinline__ void cp_commit() {
    asm volatile("cp.async.commit_group;\n" ::: "memory");
}
__device__ __forceinline__ void cp_wait1() {
    asm volatile("cp.async.wait_group 1;\n" ::: "memory");
}
__device__ __forceinline__ void cp_wait0() {
    asm volatile("cp.async.wait_group 0;\n" ::: "memory");
}

// ---------------------------------------------------------------------------
// bf16x3 split GEMM via mma.sync: C[M,N] = A[M,K] @ W[N,K]^T + bias
// CTA 128x128, 8 warps (2m x 4n), warp tile 64x32. K staged 32/double-buffered.
// SMEM arrays per stage: Ah|Al|Wh|Wl, 128 rows x 40 halves (80B stride).
// ---------------------------------------------------------------------------
#define KSTEP    32
#define NSTAGE   (D_ / KSTEP)          // 32
#define ROWH     40                     // halves per smem row (padded)
#define ARRB     (128 * ROWH * 2)       // 10240 bytes
#define STAGEB   (4 * ARRB)             // 40960
#define GSMEM    (2 * STAGEB)           // 81920

__global__ __launch_bounds__(256)
void gemm_hmma3(const __nv_bfloat16* __restrict__ Ah, const __nv_bfloat16* __restrict__ Al,
                const __nv_bfloat16* __restrict__ Wh, const __nv_bfloat16* __restrict__ Wl,
                const float* __restrict__ bias, float* __restrict__ C)
{
    extern __shared__ __align__(16) uint16_t sm[];

    const int tid = threadIdx.x;
    const int wid = tid >> 5;
    const int lane = tid & 31;
    const int g  = lane >> 2;        // 0..7
    const int t2 = (lane & 3) * 2;   // 0,2,4,6
    const int wm = wid >> 2;         // 0..1
    const int wn = wid & 3;          // 0..3
    const int bn = blockIdx.x * 128;
    const int bm = blockIdx.y * 128;

    const __nv_bfloat16* gsrc[4] = {Ah, Al, Wh, Wl};
    const int rbase[4] = {bm, bm, bn, bn};

    // ---- async stage loader: 2048 16B chunks, 8 per thread ----
    auto load_stage = [&](int s) {
        const int buf = s & 1;
        const int k0 = s * KSTEP;
        uint32_t base = smem_u32(sm) + buf * STAGEB;
#pragma unroll
        for (int i = 0; i < 8; i++) {
            int c = i * 256 + tid;
            int arr = c >> 9;            // 0..3
            int idx = c & 511;
            int row = idx >> 2;
            int q   = idx & 3;           // 16B quarter of 64B row chunk
            uint32_t dst = base + arr * ARRB + row * (ROWH * 2) + q * 16;
            const __nv_bfloat16* src =
                gsrc[arr] + (size_t)(rbase[arr] + row) * D_ + k0 + q * 8;
            cp_async16(dst, src);
        }
        cp_commit();
    };

    float acc[4][4][4];
#pragma unroll
    for (int mi = 0; mi < 4; mi++)
#pragma unroll
        for (int nj = 0; nj < 4; nj++)
#pragma unroll
            for (int r = 0; r < 4; r++) acc[mi][nj][r] = 0.0f;

    load_stage(0);
    load_stage(1);

    for (int s = 0; s < NSTAGE; s++) {
        const int buf = s & 1;
        if (s < NSTAGE - 1) cp_wait1(); else cp_wait0();
        __syncthreads();

        const uint16_t* Ah_s = sm + buf * (STAGEB / 2);
        const uint16_t* Al_s = Ah_s + ARRB / 2;
        const uint16_t* Wh_s = Ah_s + 2 * (ARRB / 2);
        const uint16_t* Wl_s = Ah_s + 3 * (ARRB / 2);

#pragma unroll
        for (int ks = 0; ks < 2; ks++) {
            const int ko = ks * 16;
            uint32_t ah[4][4], al[4][4], bh[4][2], bl[4][2];
#pragma unroll
            for (int mi = 0; mi < 4; mi++) {
                const int r0 = wm * 64 + mi * 16;
                ah[mi][0] = *(const uint32_t*)&Ah_s[(r0 + g)     * ROWH + ko + t2];
                ah[mi][1] = *(const uint32_t*)&Ah_s[(r0 + g + 8) * ROWH + ko + t2];
                ah[mi][2] = *(const uint32_t*)&Ah_s[(r0 + g)     * ROWH + ko + t2 + 8];
                ah[mi][3] = *(const uint32_t*)&Ah_s[(r0 + g + 8) * ROWH + ko + t2 + 8];
            }
#pragma unroll
            for (int nj = 0; nj < 4; nj++) {
                const int n0 = wn * 32 + nj * 8 + g;
                bh[nj][0] = *(const uint32_t*)&Wh_s[n0 * ROWH + ko + t2];
                bh[nj][1] = *(const uint32_t*)&Wh_s[n0 * ROWH + ko + t2 + 8];
            }
            // hi * hi
#pragma unroll
            for (int mi = 0; mi < 4; mi++)
#pragma unroll
                for (int nj = 0; nj < 4; nj++)
                    mma16816(acc[mi][nj], ah[mi], bh[nj]);
            // hi * lo
#pragma unroll
            for (int nj = 0; nj < 4; nj++) {
                const int n0 = wn * 32 + nj * 8 + g;
                bl[nj][0] = *(const uint32_t*)&Wl_s[n0 * ROWH + ko + t2];
                bl[nj][1] = *(const uint32_t*)&Wl_s[n0 * ROWH + ko + t2 + 8];
            }
#pragma unroll
            for (int mi = 0; mi < 4; mi++)
#pragma unroll
                for (int nj = 0; nj < 4; nj++)
                    mma16816(acc[mi][nj], ah[mi], bl[nj]);
            // lo * hi
#pragma unroll
            for (int mi = 0; mi < 4; mi++) {
                const int r0 = wm * 64 + mi * 16;
                al[mi][0] = *(const uint32_t*)&Al_s[(r0 + g)     * ROWH + ko + t2];
                al[mi][1] = *(const uint32_t*)&Al_s[(r0 + g + 8) * ROWH + ko + t2];
                al[mi][2] = *(const uint32_t*)&Al_s[(r0 + g)     * ROWH + ko + t2 + 8];
                al[mi][3] = *(const uint32_t*)&Al_s[(r0 + g + 8) * ROWH + ko + t2 + 8];
            }
#pragma unroll
            for (int mi = 0; mi < 4; mi++)
#pragma unroll
                for (int nj = 0; nj < 4; nj++)
                    mma16816(acc[mi][nj], al[mi], bh[nj]);
        }
        __syncthreads();
        if (s + 2 < NSTAGE) load_stage(s + 2);
    }

    // ---- epilogue: bias + store ----
#pragma unroll
    for (int mi = 0; mi < 4; mi++) {
        const int r0 = bm + wm * 64 + mi * 16 + g;
#pragma unroll
        for (int nj = 0; nj < 4; nj++) {
            const int c0 = bn + wn * 32 + nj * 8 + t2;
            const float b0 = bias[c0], b1 = bias[c0 + 1];
            float2 v0 = make_float2(acc[mi][nj][0] + b0, acc[mi][nj][1] + b1);
            float2 v1 = make_float2(acc[mi][nj][2] + b0, acc[mi][nj][3] + b1);
            *(float2*)&C[(size_t)r0 * D_ + c0]       = v0;
            *(float2*)&C[(size_t)(r0 + 8) * D_ + c0] = v1;
        }
    }
}

// ---------------------------------------------------------------------------
// Flash-attention (fp32, online softmax) — unchanged (converts next round).
// ---------------------------------------------------------------------------
__device__ __forceinline__ int swz(int r, int c) { return r * 64 + (c ^ (r & 31)); }

__global__ __launch_bounds__(256, 2)
void attn_kernel(const float* __restrict__ Q, const float* __restrict__ Kg,
                 const float* __restrict__ Vg, float* __restrict__ Y)
{
    __shared__ float Qs[64*64];
    __shared__ float Ks[64*64];
    __shared__ float Vs[64*64];

    const int tid = threadIdx.x;
    const int tx  = tid & 15;
    const int ty  = tid >> 4;
    const int q0  = blockIdx.x * 64;
    const int bh  = blockIdx.y;
    const int b   = bh >> 4;
    const int h   = bh & 15;

    const float* Qp = Q  + (size_t)b * S_ * D_ + (size_t)h * HD_;
    const float* Kp = Kg + (size_t)b * S_ * D_ + (size_t)h * HD_;
    const float* Vp = Vg + (size_t)b * S_ * D_ + (size_t)h * HD_;

    for (int idx = tid; idx < 64*64; idx += 256) {
        int r = idx >> 6, d = idx & 63;
        Qs[r * 64 + d] = Qp[(size_t)(q0 + r) * D_ + d];
    }

    float m_i[4], l_i[4], O[4][4];
#pragma unroll
    for (int i = 0; i < 4; i++) {
        m_i[i] = -1e30f; l_i[i] = 0.0f;
#pragma unroll
        for (int j = 0; j < 4; j++) O[i][j] = 0.0f;
    }
    __syncthreads();

    for (int k0 = 0; k0 < S_; k0 += 64) {
        for (int idx = tid; idx < 64*64; idx += 256) {
            int key = idx >> 6, d = idx & 63;
            Ks[swz(d, key)]  = Kp[(size_t)(k0 + key) * D_ + d];
            Vs[key * 64 + d] = Vp[(size_t)(k0 + key) * D_ + d];
        }
        __syncthreads();

        float s[4][4];
#pragma unroll
        for (int i = 0; i < 4; i++)
#pragma unroll
            for (int j = 0; j < 4; j++) s[i][j] = 0.0f;

#pragma unroll 8
        for (int kk = 0; kk < 64; kk++) {
            float a[4], bb[4];
#pragma unroll
            for (int i = 0; i < 4; i++) a[i]  = Qs[(ty*4 + i) * 64 + kk];
#pragma unroll
            for (int j = 0; j < 4; j++) bb[j] = Ks[swz(kk, tx*4 + j)];
#pragma unroll
            for (int i = 0; i < 4; i++)
#pragma unroll
                for (int j = 0; j < 4; j++)
                    s[i][j] += a[i] * bb[j];
        }

#pragma unroll
        for (int i = 0; i < 4; i++) {
#pragma unroll
            for (int j = 0; j < 4; j++) s[i][j] *= 0.125f;
            float rm = fmaxf(fmaxf(s[i][0], s[i][1]), fmaxf(s[i][2], s[i][3]));
#pragma unroll
            for (int off = 1; off < 16; off <<= 1)
                rm = fmaxf(rm, __shfl_xor_sync(0xffffffffu, rm, off, 16));
            float mn    = fmaxf(m_i[i], rm);
            float alpha = __expf(m_i[i] - mn);
            float rs = 0.0f;
#pragma unroll
            for (int j = 0; j < 4; j++) {
                s[i][j] = __expf(s[i][j] - mn);
                rs += s[i][j];
            }
#pragma unroll
            for (int off = 1; off < 16; off <<= 1)
                rs += __shfl_xor_sync(0xffffffffu, rs, off, 16);
            l_i[i] = l_i[i] * alpha + rs;
#pragma unroll
            for (int j = 0; j < 4; j++) O[i][j] *= alpha;
            m_i[i] = mn;
        }

        __syncthreads();
#pragma unroll
        for (int j = 0; j < 4; j++)
#pragma unroll
            for (int i = 0; i < 4; i++)
                Ks[swz(tx*4 + j, ty*4 + i)] = s[i][j];
        __syncthreads();

#pragma unroll 8
        for (int kk = 0; kk < 64; kk++) {
            float a[4], bb[4];
#pragma unroll
            for (int i = 0; i < 4; i++) a[i]  = Ks[swz(kk, ty*4 + i)];
#pragma unroll
            for (int j = 0; j < 4; j++) bb[j] = Vs[kk * 64 + tx*4 + j];
#pragma unroll
            for (int i = 0; i < 4; i++)
#pragma unroll
                for (int j = 0; j < 4; j++)
                    O[i][j] += a[i] * bb[j];
        }
        __syncthreads();
    }

#pragma unroll
    for (int i = 0; i < 4; i++) {
        float inv = 1.0f / l_i[i];
        float4 o = make_float4(O[i][0]*inv, O[i][1]*inv, O[i][2]*inv, O[i][3]*inv);
        *(float4*)&Y[(size_t)(b * S_ + q0 + ty*4 + i) * D_ + h * HD_ + tx*4] = o;
    }
}

// ---------------------------------------------------------------------------
// Launch
// ---------------------------------------------------------------------------
extern "C" void kernel_launch(void* const* d_in, const int* in_sizes, int n_in,
                              void* d_out, int out_size)
{
    const float* dec = (const float*)d_in[0];
    const float* enc = (const float*)d_in[1];
    const float* Wq  = (const float*)d_in[2];
    const float* bq  = (const float*)d_in[3];
    const float* Wk  = (const float*)d_in[4];
    const float* bk  = (const float*)d_in[5];
    const float* Wv  = (const float*)d_in[6];
    const float* bv  = (const float*)d_in[7];
    const float* Wp  = (const float*)d_in[8];
    const float* bp  = (const float*)d_in[9];
    float* out = (float*)d_out;

    float *Qd, *Kd, *Vd, *Yd;
    cudaGetSymbolAddress((void**)&Qd, g_Q);
    cudaGetSymbolAddress((void**)&Kd, g_K);
    cudaGetSymbolAddress((void**)&Vd, g_V);
    cudaGetSymbolAddress((void**)&Yd, g_Y);

    __nv_bfloat16 *decH,*decL,*encH,*encL,*yH,*yL;
    __nv_bfloat16 *wqH,*wqL,*wkH,*wkL,*wvH,*wvL,*wpH,*wpL;
    cudaGetSymbolAddress((void**)&decH, g_decH); cudaGetSymbolAddress((void**)&decL, g_decL);
    cudaGetSymbolAddress((void**)&encH, g_encH); cudaGetSymbolAddress((void**)&encL, g_encL);
    cudaGetSymbolAddress((void**)&yH,  g_yH);    cudaGetSymbolAddress((void**)&yL,  g_yL);
    cudaGetSymbolAddress((void**)&wqH, g_wqH);   cudaGetSymbolAddress((void**)&wqL, g_wqL);
    cudaGetSymbolAddress((void**)&wkH, g_wkH);   cudaGetSymbolAddress((void**)&wkL, g_wkL);
    cudaGetSymbolAddress((void**)&wvH, g_wvH);   cudaGetSymbolAddress((void**)&wvL, g_wvL);
    cudaGetSymbolAddress((void**)&wpH, g_wpH);   cudaGetSymbolAddress((void**)&wpL, g_wpL);

    cudaFuncSetAttribute(gemm_hmma3, cudaFuncAttributeMaxDynamicSharedMemorySize, GSMEM);

    const int nAct4 = M_ * D_ / 4;
    const int nW4   = D_ * D_ / 4;

    split_bf16<<<(nAct4 + 255) / 256, 256>>>(dec, decH, decL, nAct4);
    split_bf16<<<(nAct4 + 255) / 256, 256>>>(enc, encH, encL, nAct4);
    split_bf16<<<(nW4 + 255) / 256, 256>>>(Wq, wqH, wqL, nW4);
    split_bf16<<<(nW4 + 255) / 256, 256>>>(Wk, wkH, wkL, nW4);
    split_bf16<<<(nW4 + 255) / 256, 256>>>(Wv, wvH, wvL, nW4);
    split_bf16<<<(nW4 + 255) / 256, 256>>>(Wp, wpH, wpL, nW4);

    dim3 ggrid(D_ / 128, M_ / 128);   // (8, 32)
    gemm_hmma3<<<ggrid, 256, GSMEM>>>(decH, decL, wqH, wqL, bq, Qd);
    gemm_hmma3<<<ggrid, 256, GSMEM>>>(encH, encL, wkH, wkL, bk, Kd);
    gemm_hmma3<<<ggrid, 256, GSMEM>>>(encH, encL, wvH, wvL, bv, Vd);

    attn_kernel<<<dim3(S_ / 64, B_ * H_), 256>>>(Qd, Kd, Vd, Yd);

    split_bf16<<<(nAct4 + 255) / 256, 256>>>(Yd, yH, yL, nAct4);
    gemm_hmma3<<<ggrid, 256, GSMEM>>>(yH, yL, wpH, wpL, bp, out);
}

// round 5
// speedup vs baseline: 2.3119x; 1.8204x over previous
#include <cuda_runtime.h>
#include <cuda_bf16.h>
#include <cstdint>

#define B_  2
#define S_  2048
#define D_  1024
#define H_  16
#define HD_ 64
#define M_  (B_*S_)   // 4096

// ---------------------------------------------------------------------------
// Scratch (device globals: no allocations allowed). All split bf16 pairs.
// ---------------------------------------------------------------------------
__device__ __nv_bfloat16 g_decH[M_*D_], g_decL[M_*D_];
__device__ __nv_bfloat16 g_encH[M_*D_], g_encL[M_*D_];
__device__ __nv_bfloat16 g_qH[M_*D_],   g_qL[M_*D_];
__device__ __nv_bfloat16 g_kH[M_*D_],   g_kL[M_*D_];
__device__ __nv_bfloat16 g_vH[M_*D_],   g_vL[M_*D_];
__device__ __nv_bfloat16 g_yH[M_*D_],   g_yL[M_*D_];
__device__ __nv_bfloat16 g_wqH[D_*D_],  g_wqL[D_*D_];
__device__ __nv_bfloat16 g_wkH[D_*D_],  g_wkL[D_*D_];
__device__ __nv_bfloat16 g_wvH[D_*D_],  g_wvL[D_*D_];
__device__ __nv_bfloat16 g_wpH[D_*D_],  g_wpL[D_*D_];

// ---------------------------------------------------------------------------
// fp32 -> (hi, lo) bf16 split
// ---------------------------------------------------------------------------
__global__ __launch_bounds__(256)
void split_bf16(const float* __restrict__ src,
                __nv_bfloat16* __restrict__ hi,
                __nv_bfloat16* __restrict__ lo, int n4)
{
    int i = blockIdx.x * blockDim.x + threadIdx.x;
    if (i >= n4) return;
    float4 v = ((const float4*)src)[i];
    float x[4] = {v.x, v.y, v.z, v.w};
    unsigned short h[4], l[4];
#pragma unroll
    for (int j = 0; j < 4; j++) {
        __nv_bfloat16 hb = __float2bfloat16(x[j]);
        __nv_bfloat16 lb = __float2bfloat16(x[j] - __bfloat162float(hb));
        h[j] = __bfloat16_as_ushort(hb);
        l[j] = __bfloat16_as_ushort(lb);
    }
    uint2 hv, lv;
    hv.x = (uint32_t)h[0] | ((uint32_t)h[1] << 16);
    hv.y = (uint32_t)h[2] | ((uint32_t)h[3] << 16);
    lv.x = (uint32_t)l[0] | ((uint32_t)l[1] << 16);
    lv.y = (uint32_t)l[2] | ((uint32_t)l[3] << 16);
    ((uint2*)hi)[i] = hv;
    ((uint2*)lo)[i] = lv;
}

// ---------------------------------------------------------------------------
// Helpers (baseline PTX only)
// ---------------------------------------------------------------------------
__device__ __forceinline__ uint32_t smem_u32(const void* p) {
    uint32_t a;
    asm("{ .reg .u64 t; cvta.to.shared.u64 t, %1; cvt.u32.u64 %0, t; }"
        : "=r"(a) : "l"(p));
    return a;
}

__device__ __forceinline__ void mma16816(float* c, const uint32_t* a, const uint32_t* b) {
    asm volatile(
        "mma.sync.aligned.m16n8k16.row.col.f32.bf16.bf16.f32 "
        "{%0,%1,%2,%3}, {%4,%5,%6,%7}, {%8,%9}, {%0,%1,%2,%3};"
        : "+f"(c[0]), "+f"(c[1]), "+f"(c[2]), "+f"(c[3])
        : "r"(a[0]), "r"(a[1]), "r"(a[2]), "r"(a[3]), "r"(b[0]), "r"(b[1]));
}

__device__ __forceinline__ void cp_async16(uint32_t dst, const void* src) {
    asm volatile("cp.async.cg.shared.global [%0], [%1], 16;\n"
                 :: "r"(dst), "l"(src) : "memory");
}
__device__ __forceinline__ void cp_commit() {
    asm volatile("cp.async.commit_group;\n" ::: "memory");
}
__device__ __forceinline__ void cp_wait1() {
    asm volatile("cp.async.wait_group 1;\n" ::: "memory");
}
__device__ __forceinline__ void cp_wait0() {
    asm volatile("cp.async.wait_group 0;\n" ::: "memory");
}

// split two fp32 -> packed bf16x2 hi/lo (x -> low half, y -> high half)
__device__ __forceinline__ void split2(float x, float y, uint32_t& hi, uint32_t& lo) {
    __nv_bfloat16 xh = __float2bfloat16(x);
    __nv_bfloat16 yh = __float2bfloat16(y);
    __nv_bfloat16 xl = __float2bfloat16(x - __bfloat162float(xh));
    __nv_bfloat16 yl = __float2bfloat16(y - __bfloat162float(yh));
    __nv_bfloat162 hv; hv.x = xh; hv.y = yh;
    __nv_bfloat162 lv; lv.x = xl; lv.y = yl;
    hi = *(uint32_t*)&hv; lo = *(uint32_t*)&lv;
}

// ---------------------------------------------------------------------------
// bf16x3 split GEMM via mma.sync: C = A[M,K] @ W[N,K]^T + bias, then either
// fp32 store (CF) or scaled split-bf16 store (CH/CL).
// CTA 128x128, 8 warps (2m x 4n), warp tile 64x32, K staged 32, double buffer.
// ---------------------------------------------------------------------------
#define KSTEP    32
#define NSTAGE   (D_ / KSTEP)          // 32
#define ROWH     40
#define ARRB     (128 * ROWH * 2)      // 10240 bytes
#define STAGEB   (4 * ARRB)            // 40960
#define GSMEM    (2 * STAGEB)          // 81920

__global__ __launch_bounds__(256)
void gemm_hmma3(const __nv_bfloat16* __restrict__ Ah, const __nv_bfloat16* __restrict__ Al,
                const __nv_bfloat16* __restrict__ Wh, const __nv_bfloat16* __restrict__ Wl,
                const float* __restrict__ bias,
                float* __restrict__ CF,
                __nv_bfloat16* __restrict__ CH, __nv_bfloat16* __restrict__ CL,
                float scale)
{
    extern __shared__ __align__(16) uint16_t sm[];

    const int tid = threadIdx.x;
    const int wid = tid >> 5;
    const int lane = tid & 31;
    const int g  = lane >> 2;
    const int t2 = (lane & 3) * 2;
    const int wm = wid >> 2;
    const int wn = wid & 3;
    const int bn = blockIdx.x * 128;
    const int bm = blockIdx.y * 128;

    const __nv_bfloat16* gsrc[4] = {Ah, Al, Wh, Wl};
    const int rbase[4] = {bm, bm, bn, bn};

    auto load_stage = [&](int s) {
        const int buf = s & 1;
        const int k0 = s * KSTEP;
        uint32_t base = smem_u32(sm) + buf * STAGEB;
#pragma unroll
        for (int i = 0; i < 8; i++) {
            int c = i * 256 + tid;
            int arr = c >> 9;
            int idx = c & 511;
            int row = idx >> 2;
            int q   = idx & 3;
            uint32_t dst = base + arr * ARRB + row * (ROWH * 2) + q * 16;
            const __nv_bfloat16* src =
                gsrc[arr] + (size_t)(rbase[arr] + row) * D_ + k0 + q * 8;
            cp_async16(dst, src);
        }
        cp_commit();
    };

    float acc[4][4][4];
#pragma unroll
    for (int mi = 0; mi < 4; mi++)
#pragma unroll
        for (int nj = 0; nj < 4; nj++)
#pragma unroll
            for (int r = 0; r < 4; r++) acc[mi][nj][r] = 0.0f;

    load_stage(0);
    load_stage(1);

    for (int s = 0; s < NSTAGE; s++) {
        const int buf = s & 1;
        if (s < NSTAGE - 1) cp_wait1(); else cp_wait0();
        __syncthreads();

        const uint16_t* Ah_s = sm + buf * (STAGEB / 2);
        const uint16_t* Al_s = Ah_s + ARRB / 2;
        const uint16_t* Wh_s = Ah_s + 2 * (ARRB / 2);
        const uint16_t* Wl_s = Ah_s + 3 * (ARRB / 2);

#pragma unroll
        for (int ks = 0; ks < 2; ks++) {
            const int ko = ks * 16;
            uint32_t ah[4][4], al[4][4], bh[4][2], bl[4][2];
#pragma unroll
            for (int mi = 0; mi < 4; mi++) {
                const int r0 = wm * 64 + mi * 16;
                ah[mi][0] = *(const uint32_t*)&Ah_s[(r0 + g)     * ROWH + ko + t2];
                ah[mi][1] = *(const uint32_t*)&Ah_s[(r0 + g + 8) * ROWH + ko + t2];
                ah[mi][2] = *(const uint32_t*)&Ah_s[(r0 + g)     * ROWH + ko + t2 + 8];
                ah[mi][3] = *(const uint32_t*)&Ah_s[(r0 + g + 8) * ROWH + ko + t2 + 8];
            }
#pragma unroll
            for (int nj = 0; nj < 4; nj++) {
                const int n0 = wn * 32 + nj * 8 + g;
                bh[nj][0] = *(const uint32_t*)&Wh_s[n0 * ROWH + ko + t2];
                bh[nj][1] = *(const uint32_t*)&Wh_s[n0 * ROWH + ko + t2 + 8];
            }
#pragma unroll
            for (int mi = 0; mi < 4; mi++)
#pragma unroll
                for (int nj = 0; nj < 4; nj++)
                    mma16816(acc[mi][nj], ah[mi], bh[nj]);
#pragma unroll
            for (int nj = 0; nj < 4; nj++) {
                const int n0 = wn * 32 + nj * 8 + g;
                bl[nj][0] = *(const uint32_t*)&Wl_s[n0 * ROWH + ko + t2];
                bl[nj][1] = *(const uint32_t*)&Wl_s[n0 * ROWH + ko + t2 + 8];
            }
#pragma unroll
            for (int mi = 0; mi < 4; mi++)
#pragma unroll
                for (int nj = 0; nj < 4; nj++)
                    mma16816(acc[mi][nj], ah[mi], bl[nj]);
#pragma unroll
            for (int mi = 0; mi < 4; mi++) {
                const int r0 = wm * 64 + mi * 16;
                al[mi][0] = *(const uint32_t*)&Al_s[(r0 + g)     * ROWH + ko + t2];
                al[mi][1] = *(const uint32_t*)&Al_s[(r0 + g + 8) * ROWH + ko + t2];
                al[mi][2] = *(const uint32_t*)&Al_s[(r0 + g)     * ROWH + ko + t2 + 8];
                al[mi][3] = *(const uint32_t*)&Al_s[(r0 + g + 8) * ROWH + ko + t2 + 8];
            }
#pragma unroll
            for (int mi = 0; mi < 4; mi++)
#pragma unroll
                for (int nj = 0; nj < 4; nj++)
                    mma16816(acc[mi][nj], al[mi], bh[nj]);
        }
        __syncthreads();
        if (s + 2 < NSTAGE) load_stage(s + 2);
    }

    // ---- epilogue ----
#pragma unroll
    for (int mi = 0; mi < 4; mi++) {
        const int r0 = bm + wm * 64 + mi * 16 + g;
#pragma unroll
        for (int nj = 0; nj < 4; nj++) {
            const int c0 = bn + wn * 32 + nj * 8 + t2;
            const float b0 = bias[c0], b1 = bias[c0 + 1];
            float v00 = acc[mi][nj][0] + b0, v01 = acc[mi][nj][1] + b1;
            float v10 = acc[mi][nj][2] + b0, v11 = acc[mi][nj][3] + b1;
            if (CF) {
                *(float2*)&CF[(size_t)r0 * D_ + c0]       = make_float2(v00, v01);
                *(float2*)&CF[(size_t)(r0 + 8) * D_ + c0] = make_float2(v10, v11);
            } else {
                uint32_t h0, l0, h1, l1;
                split2(v00 * scale, v01 * scale, h0, l0);
                split2(v10 * scale, v11 * scale, h1, l1);
                *(uint32_t*)&CH[(size_t)r0 * D_ + c0]       = h0;
                *(uint32_t*)&CL[(size_t)r0 * D_ + c0]       = l0;
                *(uint32_t*)&CH[(size_t)(r0 + 8) * D_ + c0] = h1;
                *(uint32_t*)&CL[(size_t)(r0 + 8) * D_ + c0] = l1;
            }
        }
    }
}

// ---------------------------------------------------------------------------
// HMMA flash-attention, bf16x3 on both GEMMs.
// CTA: 128 queries of one (b,h); 8 warps x 16 queries; key tiles of 64.
// Q fragments loaded from gmem once (pre-scaled by 0.125 in Q projection).
// K smem natural [key][dim] (= B col-major for QK^T); V transposed to
// Vt[dim][key] (= B col-major for PV). Row stride 72 halves: fragment
// reads conflict-free (bank = 4g + t2/2).
// ---------------------------------------------------------------------------
__global__ __launch_bounds__(256)
void attn_hmma(const __nv_bfloat16* __restrict__ qH, const __nv_bfloat16* __restrict__ qL,
               const __nv_bfloat16* __restrict__ kH, const __nv_bfloat16* __restrict__ kL,
               const __nv_bfloat16* __restrict__ vH, const __nv_bfloat16* __restrict__ vL,
               __nv_bfloat16* __restrict__ yH, __nv_bfloat16* __restrict__ yL)
{
    __shared__ __align__(16) uint16_t Ks[2][64*72];  // [h/l][key][dim]
    __shared__ __align__(16) uint16_t Vt[2][64*72];  // [h/l][dim][key]

    const int tid  = threadIdx.x;
    const int wid  = tid >> 5;
    const int lane = tid & 31;
    const int g    = lane >> 2;
    const int t2   = (lane & 3) * 2;
    const int q0   = blockIdx.x * 128;
    const int bh   = blockIdx.y;
    const int b    = bh >> 4;
    const int h    = bh & 15;
    const int col0 = h * HD_;
    const int m0   = b * S_ + q0 + wid * 16;   // warp's first query row

    // ---- Q fragments (held in registers for the whole kernel) ----
    uint32_t qh[4][4], ql[4][4];
    {
        const __nv_bfloat16* r0h = qH + (size_t)(m0 + g) * D_ + col0;
        const __nv_bfloat16* r1h = qH + (size_t)(m0 + g + 8) * D_ + col0;
        const __nv_bfloat16* r0l = qL + (size_t)(m0 + g) * D_ + col0;
        const __nv_bfloat16* r1l = qL + (size_t)(m0 + g + 8) * D_ + col0;
#pragma unroll
        for (int kc = 0; kc < 4; kc++) {
            qh[kc][0] = *(const uint32_t*)(r0h + kc * 16 + t2);
            qh[kc][1] = *(const uint32_t*)(r1h + kc * 16 + t2);
            qh[kc][2] = *(const uint32_t*)(r0h + kc * 16 + t2 + 8);
            qh[kc][3] = *(const uint32_t*)(r1h + kc * 16 + t2 + 8);
            ql[kc][0] = *(const uint32_t*)(r0l + kc * 16 + t2);
            ql[kc][1] = *(const uint32_t*)(r1l + kc * 16 + t2);
            ql[kc][2] = *(const uint32_t*)(r0l + kc * 16 + t2 + 8);
            ql[kc][3] = *(const uint32_t*)(r1l + kc * 16 + t2 + 8);
        }
    }

    float of[8][4];
#pragma unroll
    for (int j = 0; j < 8; j++)
#pragma unroll
        for (int r = 0; r < 4; r++) of[j][r] = 0.0f;
    float mr0 = -1e30f, mr1 = -1e30f, lr0 = 0.0f, lr1 = 0.0f;

    for (int kb = 0; kb < S_; kb += 64) {
        __syncthreads();   // previous tile fully consumed
        // ---- K tiles: 1024 16B chunks (coalesced) ----
#pragma unroll
        for (int i = 0; i < 4; i++) {
            int c = i * 256 + tid;
            int a = c >> 9;
            int idx = c & 511;
            int row = idx >> 3, qq = idx & 7;
            const __nv_bfloat16* src = (a ? kL : kH)
                + (size_t)(b * S_ + kb + row) * D_ + col0 + qq * 8;
            *(float4*)&Ks[a][row * 72 + qq * 8] = *(const float4*)src;
        }
        // ---- V tiles transposed: 4096 u32 elements ----
#pragma unroll
        for (int i = 0; i < 16; i++) {
            int u = i * 256 + tid;
            int a = u >> 11;
            int v = u & 2047;
            int key = v & 63, dpi = v >> 6;     // dpi: 0..31 (dim pair)
            uint32_t w = *(const uint32_t*)((a ? vL : vH)
                + (size_t)(b * S_ + kb + key) * D_ + col0 + dpi * 2);
            Vt[a][(2 * dpi)     * 72 + key] = (uint16_t)(w & 0xffff);
            Vt[a][(2 * dpi + 1) * 72 + key] = (uint16_t)(w >> 16);
        }
        __syncthreads();

        // ---- S = Q K^T (3 split terms) ----
        float sf[8][4];
#pragma unroll
        for (int j = 0; j < 8; j++)
#pragma unroll
            for (int r = 0; r < 4; r++) sf[j][r] = 0.0f;

#pragma unroll
        for (int kc = 0; kc < 4; kc++) {
#pragma unroll
            for (int j = 0; j < 8; j++) {
                uint32_t bhf[2], blf[2];
                const int n0 = j * 8 + g;
                bhf[0] = *(const uint32_t*)&Ks[0][n0 * 72 + kc * 16 + t2];
                bhf[1] = *(const uint32_t*)&Ks[0][n0 * 72 + kc * 16 + t2 + 8];
                blf[0] = *(const uint32_t*)&Ks[1][n0 * 72 + kc * 16 + t2];
                blf[1] = *(const uint32_t*)&Ks[1][n0 * 72 + kc * 16 + t2 + 8];
                mma16816(sf[j], qh[kc], bhf);
                mma16816(sf[j], qh[kc], blf);
                mma16816(sf[j], ql[kc], bhf);
            }
        }

        // ---- online softmax (rows g and g+8; quad = 4 lanes share a row) ----
        float tm0 = -1e30f, tm1 = -1e30f;
#pragma unroll
        for (int j = 0; j < 8; j++) {
            tm0 = fmaxf(tm0, fmaxf(sf[j][0], sf[j][1]));
            tm1 = fmaxf(tm1, fmaxf(sf[j][2], sf[j][3]));
        }
        tm0 = fmaxf(tm0, __shfl_xor_sync(0xffffffffu, tm0, 1));
        tm0 = fmaxf(tm0, __shfl_xor_sync(0xffffffffu, tm0, 2));
        tm1 = fmaxf(tm1, __shfl_xor_sync(0xffffffffu, tm1, 1));
        tm1 = fmaxf(tm1, __shfl_xor_sync(0xffffffffu, tm1, 2));
        const float mn0 = fmaxf(mr0, tm0);
        const float mn1 = fmaxf(mr1, tm1);
        const float al0 = __expf(mr0 - mn0);
        const float al1 = __expf(mr1 - mn1);
        float rs0 = 0.0f, rs1 = 0.0f;
#pragma unroll
        for (int j = 0; j < 8; j++) {
            sf[j][0] = __expf(sf[j][0] - mn0);
            sf[j][1] = __expf(sf[j][1] - mn0);
            sf[j][2] = __expf(sf[j][2] - mn1);
            sf[j][3] = __expf(sf[j][3] - mn1);
            rs0 += sf[j][0] + sf[j][1];
            rs1 += sf[j][2] + sf[j][3];
        }
        rs0 += __shfl_xor_sync(0xffffffffu, rs0, 1);
        rs0 += __shfl_xor_sync(0xffffffffu, rs0, 2);
        rs1 += __shfl_xor_sync(0xffffffffu, rs1, 1);
        rs1 += __shfl_xor_sync(0xffffffffu, rs1, 2);
        lr0 = lr0 * al0 + rs0;
        lr1 = lr1 * al1 + rs1;
        mr0 = mn0; mr1 = mn1;
#pragma unroll
        for (int j = 0; j < 8; j++) {
            of[j][0] *= al0; of[j][1] *= al0;
            of[j][2] *= al1; of[j][3] *= al1;
        }

        // ---- P split (registers) + O += P V (3 split terms) ----
#pragma unroll
        for (int kc = 0; kc < 4; kc++) {
            uint32_t pah[4], pal[4];
            // A-frag k-chunk kc = key cols of n-tiles 2kc (low 8) / 2kc+1 (high 8)
            split2(sf[2*kc][0],   sf[2*kc][1],   pah[0], pal[0]);   // row g,   k lo
            split2(sf[2*kc][2],   sf[2*kc][3],   pah[1], pal[1]);   // row g+8, k lo
            split2(sf[2*kc+1][0], sf[2*kc+1][1], pah[2], pal[2]);   // row g,   k hi
            split2(sf[2*kc+1][2], sf[2*kc+1][3], pah[3], pal[3]);   // row g+8, k hi
#pragma unroll
            for (int j = 0; j < 8; j++) {
                uint32_t vhf[2], vlf[2];
                const int n0 = j * 8 + g;   // output dim
                vhf[0] = *(const uint32_t*)&Vt[0][n0 * 72 + kc * 16 + t2];
                vhf[1] = *(const uint32_t*)&Vt[0][n0 * 72 + kc * 16 + t2 + 8];
                vlf[0] = *(const uint32_t*)&Vt[1][n0 * 72 + kc * 16 + t2];
                vlf[1] = *(const uint32_t*)&Vt[1][n0 * 72 + kc * 16 + t2 + 8];
                mma16816(of[j], pah, vhf);
                mma16816(of[j], pah, vlf);
                mma16816(of[j], pal, vhf);
            }
        }
    }

    // ---- epilogue: normalize, split, store Y ----
    const float inv0 = 1.0f / lr0;
    const float inv1 = 1.0f / lr1;
#pragma unroll
    for (int j = 0; j < 8; j++) {
        uint32_t h0, l0, h1, l1;
        split2(of[j][0] * inv0, of[j][1] * inv0, h0, l0);
        split2(of[j][2] * inv1, of[j][3] * inv1, h1, l1);
        const size_t o0 = (size_t)(m0 + g) * D_ + col0 + j * 8 + t2;
        const size_t o1 = (size_t)(m0 + g + 8) * D_ + col0 + j * 8 + t2;
        *(uint32_t*)&yH[o0] = h0;
        *(uint32_t*)&yL[o0] = l0;
        *(uint32_t*)&yH[o1] = h1;
        *(uint32_t*)&yL[o1] = l1;
    }
}

// ---------------------------------------------------------------------------
// Launch
// ---------------------------------------------------------------------------
extern "C" void kernel_launch(void* const* d_in, const int* in_sizes, int n_in,
                              void* d_out, int out_size)
{
    const float* dec = (const float*)d_in[0];
    const float* enc = (const float*)d_in[1];
    const float* Wq  = (const float*)d_in[2];
    const float* bq  = (const float*)d_in[3];
    const float* Wk  = (const float*)d_in[4];
    const float* bk  = (const float*)d_in[5];
    const float* Wv  = (const float*)d_in[6];
    const float* bv  = (const float*)d_in[7];
    const float* Wp  = (const float*)d_in[8];
    const float* bp  = (const float*)d_in[9];
    float* out = (float*)d_out;

    __nv_bfloat16 *decH,*decL,*encH,*encL;
    __nv_bfloat16 *qHp,*qLp,*kHp,*kLp,*vHp,*vLp,*yHp,*yLp;
    __nv_bfloat16 *wqH,*wqL,*wkH,*wkL,*wvH,*wvL,*wpH,*wpL;
    cudaGetSymbolAddress((void**)&decH, g_decH); cudaGetSymbolAddress((void**)&decL, g_decL);
    cudaGetSymbolAddress((void**)&encH, g_encH); cudaGetSymbolAddress((void**)&encL, g_encL);
    cudaGetSymbolAddress((void**)&qHp, g_qH);   cudaGetSymbolAddress((void**)&qLp, g_qL);
    cudaGetSymbolAddress((void**)&kHp, g_kH);   cudaGetSymbolAddress((void**)&kLp, g_kL);
    cudaGetSymbolAddress((void**)&vHp, g_vH);   cudaGetSymbolAddress((void**)&vLp, g_vL);
    cudaGetSymbolAddress((void**)&yHp, g_yH);   cudaGetSymbolAddress((void**)&yLp, g_yL);
    cudaGetSymbolAddress((void**)&wqH, g_wqH);  cudaGetSymbolAddress((void**)&wqL, g_wqL);
    cudaGetSymbolAddress((void**)&wkH, g_wkH);  cudaGetSymbolAddress((void**)&wkL, g_wkL);
    cudaGetSymbolAddress((void**)&wvH, g_wvH);  cudaGetSymbolAddress((void**)&wvL, g_wvL);
    cudaGetSymbolAddress((void**)&wpH, g_wpH);  cudaGetSymbolAddress((void**)&wpL, g_wpL);

    cudaFuncSetAttribute(gemm_hmma3, cudaFuncAttributeMaxDynamicSharedMemorySize, GSMEM);

    const int nAct4 = M_ * D_ / 4;
    const int nW4   = D_ * D_ / 4;

    split_bf16<<<(nAct4 + 255) / 256, 256>>>(dec, decH, decL, nAct4);
    split_bf16<<<(nAct4 + 255) / 256, 256>>>(enc, encH, encL, nAct4);
    split_bf16<<<(nW4 + 255) / 256, 256>>>(Wq, wqH, wqL, nW4);
    split_bf16<<<(nW4 + 255) / 256, 256>>>(Wk, wkH, wkL, nW4);
    split_bf16<<<(nW4 + 255) / 256, 256>>>(Wv, wvH, wvL, nW4);
    split_bf16<<<(nW4 + 255) / 256, 256>>>(Wp, wpH, wpL, nW4);

    dim3 ggrid(D_ / 128, M_ / 128);   // (8, 32)
    // Q projection pre-scaled by 1/sqrt(HD)=0.125 (exact power of two)
    gemm_hmma3<<<ggrid, 256, GSMEM>>>(decH, decL, wqH, wqL, bq,
                                      nullptr, qHp, qLp, 0.125f);
    gemm_hmma3<<<ggrid, 256, GSMEM>>>(encH, encL, wkH, wkL, bk,
                                      nullptr, kHp, kLp, 1.0f);
    gemm_hmma3<<<ggrid, 256, GSMEM>>>(encH, encL, wvH, wvL, bv,
                                      nullptr, vHp, vLp, 1.0f);

    attn_hmma<<<dim3(S_ / 128, B_ * H_), 256>>>(qHp, qLp, kHp, kLp, vHp, vLp,
                                                yHp, yLp);

    gemm_hmma3<<<ggrid, 256, GSMEM>>>(yHp, yLp, wpH, wpL, bp,
                                      out, nullptr, nullptr, 1.0f);
}

// round 6
// speedup vs baseline: 2.3494x; 1.0162x over previous
#include <cuda_runtime.h>
#include <cuda_bf16.h>
#include <cstdint>

#define B_  2
#define S_  2048
#define D_  1024
#define H_  16
#define HD_ 64
#define M_  (B_*S_)   // 4096

// ---------------------------------------------------------------------------
// Scratch (device globals: no allocations allowed). All split bf16 pairs.
// ---------------------------------------------------------------------------
__device__ __nv_bfloat16 g_decH[M_*D_], g_decL[M_*D_];
__device__ __nv_bfloat16 g_encH[M_*D_], g_encL[M_*D_];
__device__ __nv_bfloat16 g_qH[M_*D_],   g_qL[M_*D_];
__device__ __nv_bfloat16 g_kH[M_*D_],   g_kL[M_*D_];
__device__ __nv_bfloat16 g_vH[M_*D_],   g_vL[M_*D_];
__device__ __nv_bfloat16 g_yH[M_*D_],   g_yL[M_*D_];
__device__ __nv_bfloat16 g_wqH[D_*D_],  g_wqL[D_*D_];
__device__ __nv_bfloat16 g_wkH[D_*D_],  g_wkL[D_*D_];
__device__ __nv_bfloat16 g_wvH[D_*D_],  g_wvL[D_*D_];
__device__ __nv_bfloat16 g_wpH[D_*D_],  g_wpL[D_*D_];

// ---------------------------------------------------------------------------
// fp32 -> (hi, lo) bf16 split
// ---------------------------------------------------------------------------
__global__ __launch_bounds__(256)
void split_bf16(const float* __restrict__ src,
                __nv_bfloat16* __restrict__ hi,
                __nv_bfloat16* __restrict__ lo, int n4)
{
    int i = blockIdx.x * blockDim.x + threadIdx.x;
    if (i >= n4) return;
    float4 v = ((const float4*)src)[i];
    float x[4] = {v.x, v.y, v.z, v.w};
    unsigned short h[4], l[4];
#pragma unroll
    for (int j = 0; j < 4; j++) {
        __nv_bfloat16 hb = __float2bfloat16(x[j]);
        __nv_bfloat16 lb = __float2bfloat16(x[j] - __bfloat162float(hb));
        h[j] = __bfloat16_as_ushort(hb);
        l[j] = __bfloat16_as_ushort(lb);
    }
    uint2 hv, lv;
    hv.x = (uint32_t)h[0] | ((uint32_t)h[1] << 16);
    hv.y = (uint32_t)h[2] | ((uint32_t)h[3] << 16);
    lv.x = (uint32_t)l[0] | ((uint32_t)l[1] << 16);
    lv.y = (uint32_t)l[2] | ((uint32_t)l[3] << 16);
    ((uint2*)hi)[i] = hv;
    ((uint2*)lo)[i] = lv;
}

// ---------------------------------------------------------------------------
// Helpers (baseline PTX only)
// ---------------------------------------------------------------------------
__device__ __forceinline__ uint32_t smem_u32(const void* p) {
    uint32_t a;
    asm("{ .reg .u64 t; cvta.to.shared.u64 t, %1; cvt.u32.u64 %0, t; }"
        : "=r"(a) : "l"(p));
    return a;
}

__device__ __forceinline__ void mma16816(float* c, const uint32_t* a, const uint32_t* b) {
    asm volatile(
        "mma.sync.aligned.m16n8k16.row.col.f32.bf16.bf16.f32 "
        "{%0,%1,%2,%3}, {%4,%5,%6,%7}, {%8,%9}, {%0,%1,%2,%3};"
        : "+f"(c[0]), "+f"(c[1]), "+f"(c[2]), "+f"(c[3])
        : "r"(a[0]), "r"(a[1]), "r"(a[2]), "r"(a[3]), "r"(b[0]), "r"(b[1]));
}

__device__ __forceinline__ void cp_async16(uint32_t dst, const void* src) {
    asm volatile("cp.async.cg.shared.global [%0], [%1], 16;\n"
                 :: "r"(dst), "l"(src) : "memory");
}
__device__ __forceinline__ void cp_commit() {
    asm volatile("cp.async.commit_group;\n" ::: "memory");
}
__device__ __forceinline__ void cp_wait1() {
    asm volatile("cp.async.wait_group 1;\n" ::: "memory");
}
__device__ __forceinline__ void cp_wait0() {
    asm volatile("cp.async.wait_group 0;\n" ::: "memory");
}

// split two fp32 -> packed bf16x2 hi/lo
__device__ __forceinline__ void split2(float x, float y, uint32_t& hi, uint32_t& lo) {
    __nv_bfloat16 xh = __float2bfloat16(x);
    __nv_bfloat16 yh = __float2bfloat16(y);
    __nv_bfloat16 xl = __float2bfloat16(x - __bfloat162float(xh));
    __nv_bfloat16 yl = __float2bfloat16(y - __bfloat162float(yh));
    __nv_bfloat162 hv; hv.x = xh; hv.y = yh;
    __nv_bfloat162 lv; lv.x = xl; lv.y = yl;
    hi = *(uint32_t*)&hv; lo = *(uint32_t*)&lv;
}

// ---------------------------------------------------------------------------
// bf16x3 split GEMM (unchanged from round 4 — known good).
// ---------------------------------------------------------------------------
#define KSTEP    32
#define NSTAGE   (D_ / KSTEP)
#define ROWH     40
#define ARRB     (128 * ROWH * 2)
#define STAGEB   (4 * ARRB)
#define GSMEM    (2 * STAGEB)

__global__ __launch_bounds__(256)
void gemm_hmma3(const __nv_bfloat16* __restrict__ Ah, const __nv_bfloat16* __restrict__ Al,
                const __nv_bfloat16* __restrict__ Wh, const __nv_bfloat16* __restrict__ Wl,
                const float* __restrict__ bias,
                float* __restrict__ CF,
                __nv_bfloat16* __restrict__ CH, __nv_bfloat16* __restrict__ CL,
                float scale)
{
    extern __shared__ __align__(16) uint16_t sm[];

    const int tid = threadIdx.x;
    const int wid = tid >> 5;
    const int lane = tid & 31;
    const int g  = lane >> 2;
    const int t2 = (lane & 3) * 2;
    const int wm = wid >> 2;
    const int wn = wid & 3;
    const int bn = blockIdx.x * 128;
    const int bm = blockIdx.y * 128;

    const __nv_bfloat16* gsrc[4] = {Ah, Al, Wh, Wl};
    const int rbase[4] = {bm, bm, bn, bn};

    auto load_stage = [&](int s) {
        const int buf = s & 1;
        const int k0 = s * KSTEP;
        uint32_t base = smem_u32(sm) + buf * STAGEB;
#pragma unroll
        for (int i = 0; i < 8; i++) {
            int c = i * 256 + tid;
            int arr = c >> 9;
            int idx = c & 511;
            int row = idx >> 2;
            int q   = idx & 3;
            uint32_t dst = base + arr * ARRB + row * (ROWH * 2) + q * 16;
            const __nv_bfloat16* src =
                gsrc[arr] + (size_t)(rbase[arr] + row) * D_ + k0 + q * 8;
            cp_async16(dst, src);
        }
        cp_commit();
    };

    float acc[4][4][4];
#pragma unroll
    for (int mi = 0; mi < 4; mi++)
#pragma unroll
        for (int nj = 0; nj < 4; nj++)
#pragma unroll
            for (int r = 0; r < 4; r++) acc[mi][nj][r] = 0.0f;

    load_stage(0);
    load_stage(1);

    for (int s = 0; s < NSTAGE; s++) {
        const int buf = s & 1;
        if (s < NSTAGE - 1) cp_wait1(); else cp_wait0();
        __syncthreads();

        const uint16_t* Ah_s = sm + buf * (STAGEB / 2);
        const uint16_t* Al_s = Ah_s + ARRB / 2;
        const uint16_t* Wh_s = Ah_s + 2 * (ARRB / 2);
        const uint16_t* Wl_s = Ah_s + 3 * (ARRB / 2);

#pragma unroll
        for (int ks = 0; ks < 2; ks++) {
            const int ko = ks * 16;
            uint32_t ah[4][4], al[4][4], bh[4][2], bl[4][2];
#pragma unroll
            for (int mi = 0; mi < 4; mi++) {
                const int r0 = wm * 64 + mi * 16;
                ah[mi][0] = *(const uint32_t*)&Ah_s[(r0 + g)     * ROWH + ko + t2];
                ah[mi][1] = *(const uint32_t*)&Ah_s[(r0 + g + 8) * ROWH + ko + t2];
                ah[mi][2] = *(const uint32_t*)&Ah_s[(r0 + g)     * ROWH + ko + t2 + 8];
                ah[mi][3] = *(const uint32_t*)&Ah_s[(r0 + g + 8) * ROWH + ko + t2 + 8];
            }
#pragma unroll
            for (int nj = 0; nj < 4; nj++) {
                const int n0 = wn * 32 + nj * 8 + g;
                bh[nj][0] = *(const uint32_t*)&Wh_s[n0 * ROWH + ko + t2];
                bh[nj][1] = *(const uint32_t*)&Wh_s[n0 * ROWH + ko + t2 + 8];
            }
#pragma unroll
            for (int mi = 0; mi < 4; mi++)
#pragma unroll
                for (int nj = 0; nj < 4; nj++)
                    mma16816(acc[mi][nj], ah[mi], bh[nj]);
#pragma unroll
            for (int nj = 0; nj < 4; nj++) {
                const int n0 = wn * 32 + nj * 8 + g;
                bl[nj][0] = *(const uint32_t*)&Wl_s[n0 * ROWH + ko + t2];
                bl[nj][1] = *(const uint32_t*)&Wl_s[n0 * ROWH + ko + t2 + 8];
            }
#pragma unroll
            for (int mi = 0; mi < 4; mi++)
#pragma unroll
                for (int nj = 0; nj < 4; nj++)
                    mma16816(acc[mi][nj], ah[mi], bl[nj]);
#pragma unroll
            for (int mi = 0; mi < 4; mi++) {
                const int r0 = wm * 64 + mi * 16;
                al[mi][0] = *(const uint32_t*)&Al_s[(r0 + g)     * ROWH + ko + t2];
                al[mi][1] = *(const uint32_t*)&Al_s[(r0 + g + 8) * ROWH + ko + t2];
                al[mi][2] = *(const uint32_t*)&Al_s[(r0 + g)     * ROWH + ko + t2 + 8];
                al[mi][3] = *(const uint32_t*)&Al_s[(r0 + g + 8) * ROWH + ko + t2 + 8];
            }
#pragma unroll
            for (int mi = 0; mi < 4; mi++)
#pragma unroll
                for (int nj = 0; nj < 4; nj++)
                    mma16816(acc[mi][nj], al[mi], bh[nj]);
        }
        __syncthreads();
        if (s + 2 < NSTAGE) load_stage(s + 2);
    }

#pragma unroll
    for (int mi = 0; mi < 4; mi++) {
        const int r0 = bm + wm * 64 + mi * 16 + g;
#pragma unroll
        for (int nj = 0; nj < 4; nj++) {
            const int c0 = bn + wn * 32 + nj * 8 + t2;
            const float b0 = bias[c0], b1 = bias[c0 + 1];
            float v00 = acc[mi][nj][0] + b0, v01 = acc[mi][nj][1] + b1;
            float v10 = acc[mi][nj][2] + b0, v11 = acc[mi][nj][3] + b1;
            if (CF) {
                *(float2*)&CF[(size_t)r0 * D_ + c0]       = make_float2(v00, v01);
                *(float2*)&CF[(size_t)(r0 + 8) * D_ + c0] = make_float2(v10, v11);
            } else {
                uint32_t h0, l0, h1, l1;
                split2(v00 * scale, v01 * scale, h0, l0);
                split2(v10 * scale, v11 * scale, h1, l1);
                *(uint32_t*)&CH[(size_t)r0 * D_ + c0]       = h0;
                *(uint32_t*)&CL[(size_t)r0 * D_ + c0]       = l0;
                *(uint32_t*)&CH[(size_t)(r0 + 8) * D_ + c0] = h1;
                *(uint32_t*)&CL[(size_t)(r0 + 8) * D_ + c0] = l1;
            }
        }
    }
}

// ---------------------------------------------------------------------------
// Pipelined HMMA flash-attention (bf16x3 on both GEMMs).
// Double-buffered smem tiles: K via cp.async, V via register prefetch + STS.
// One __syncthreads per tile. Dep-chain broken via j-groups of 4.
// ---------------------------------------------------------------------------
#define AT_ARR   4608                   // 64*72 halves per array
#define AT_SMEM  (8 * AT_ARR * 2)       // 73728 bytes (2 buf x {Kh,Kl,Vh,Vl})
#define NTILE_   (S_ / 64)              // 32

__global__ __launch_bounds__(256)
void attn_hmma(const __nv_bfloat16* __restrict__ qH, const __nv_bfloat16* __restrict__ qL,
               const __nv_bfloat16* __restrict__ kH, const __nv_bfloat16* __restrict__ kL,
               const __nv_bfloat16* __restrict__ vH, const __nv_bfloat16* __restrict__ vL,
               __nv_bfloat16* __restrict__ yH, __nv_bfloat16* __restrict__ yL)
{
    extern __shared__ __align__(16) uint16_t sm[];
    // layout (halves): [buf*2 + a] * AT_ARR -> K arrays ; 4*AT_ARR + ... -> V
    const int tid  = threadIdx.x;
    const int wid  = tid >> 5;
    const int lane = tid & 31;
    const int g    = lane >> 2;
    const int t2   = (lane & 3) * 2;
    const int q0   = blockIdx.x * 128;
    const int bh   = blockIdx.y;
    const int b    = bh >> 4;
    const int h    = bh & 15;
    const int col0 = h * HD_;
    const int m0   = b * S_ + q0 + wid * 16;

    // ---- Q fragments (registers, whole kernel) ----
    uint32_t qh[4][4], ql[4][4];
    {
        const __nv_bfloat16* r0h = qH + (size_t)(m0 + g) * D_ + col0;
        const __nv_bfloat16* r1h = qH + (size_t)(m0 + g + 8) * D_ + col0;
        const __nv_bfloat16* r0l = qL + (size_t)(m0 + g) * D_ + col0;
        const __nv_bfloat16* r1l = qL + (size_t)(m0 + g + 8) * D_ + col0;
#pragma unroll
        for (int kc = 0; kc < 4; kc++) {
            qh[kc][0] = *(const uint32_t*)(r0h + kc * 16 + t2);
            qh[kc][1] = *(const uint32_t*)(r1h + kc * 16 + t2);
            qh[kc][2] = *(const uint32_t*)(r0h + kc * 16 + t2 + 8);
            qh[kc][3] = *(const uint32_t*)(r1h + kc * 16 + t2 + 8);
            ql[kc][0] = *(const uint32_t*)(r0l + kc * 16 + t2);
            ql[kc][1] = *(const uint32_t*)(r1l + kc * 16 + t2);
            ql[kc][2] = *(const uint32_t*)(r0l + kc * 16 + t2 + 8);
            ql[kc][3] = *(const uint32_t*)(r1l + kc * 16 + t2 + 8);
        }
    }

    // ---- loaders ----
    const uint32_t smb = smem_u32(sm);
    auto loadK = [&](int kb, int buf) {
#pragma unroll
        for (int i = 0; i < 4; i++) {
            int c = i * 256 + tid;
            int a = c >> 9;
            int idx = c & 511;
            int row = idx >> 3, qq = idx & 7;
            uint32_t dst = smb + ((buf * 2 + a) * AT_ARR + row * 72 + qq * 8) * 2;
            const __nv_bfloat16* src = (a ? kL : kH)
                + (size_t)(b * S_ + kb + row) * D_ + col0 + qq * 8;
            cp_async16(dst, src);
        }
        cp_commit();
    };
    auto loadV = [&](int kb, uint32_t* vr) {
#pragma unroll
        for (int i = 0; i < 16; i++) {
            int u = i * 256 + tid;
            int a = u >> 11;
            int v = u & 2047;
            int key = v & 63, dpi = v >> 6;
            vr[i] = *(const uint32_t*)((a ? vL : vH)
                + (size_t)(b * S_ + kb + key) * D_ + col0 + dpi * 2);
        }
    };
    auto stsV = [&](int buf, const uint32_t* vr) {
#pragma unroll
        for (int i = 0; i < 16; i++) {
            int u = i * 256 + tid;
            int a = u >> 11;
            int v = u & 2047;
            int key = v & 63, dpi = v >> 6;
            uint16_t* dst = sm + (4 + buf * 2 + a) * AT_ARR;
            dst[(2 * dpi)     * 72 + key] = (uint16_t)(vr[i] & 0xffff);
            dst[(2 * dpi + 1) * 72 + key] = (uint16_t)(vr[i] >> 16);
        }
    };

    float of[8][4];
#pragma unroll
    for (int j = 0; j < 8; j++)
#pragma unroll
        for (int r = 0; r < 4; r++) of[j][r] = 0.0f;
    float mr0 = -1e30f, mr1 = -1e30f, lr0 = 0.0f, lr1 = 0.0f;

    uint32_t vcur[16], vnxt[16];
    loadK(0, 0);
    loadV(0, vcur);

    for (int it = 0; it < NTILE_; it++) {
        const int buf = it & 1;
        cp_wait0();
        stsV(buf, vcur);
        __syncthreads();
        if (it + 1 < NTILE_) {
            loadK((it + 1) * 64, buf ^ 1);
            loadV((it + 1) * 64, vnxt);
        }

        const uint16_t* Ks0 = sm + (buf * 2 + 0) * AT_ARR;
        const uint16_t* Ks1 = sm + (buf * 2 + 1) * AT_ARR;
        const uint16_t* Vt0 = sm + (4 + buf * 2 + 0) * AT_ARR;
        const uint16_t* Vt1 = sm + (4 + buf * 2 + 1) * AT_ARR;

        // ---- S = Q K^T (3 split terms, j-groups of 4) ----
        float sf[8][4];
#pragma unroll
        for (int j = 0; j < 8; j++)
#pragma unroll
            for (int r = 0; r < 4; r++) sf[j][r] = 0.0f;

#pragma unroll
        for (int kc = 0; kc < 4; kc++) {
#pragma unroll
            for (int jg = 0; jg < 2; jg++) {
                uint32_t bhf[4][2], blf[4][2];
#pragma unroll
                for (int j4 = 0; j4 < 4; j4++) {
                    const int n0 = (jg * 4 + j4) * 8 + g;
                    bhf[j4][0] = *(const uint32_t*)&Ks0[n0 * 72 + kc * 16 + t2];
                    bhf[j4][1] = *(const uint32_t*)&Ks0[n0 * 72 + kc * 16 + t2 + 8];
                    blf[j4][0] = *(const uint32_t*)&Ks1[n0 * 72 + kc * 16 + t2];
                    blf[j4][1] = *(const uint32_t*)&Ks1[n0 * 72 + kc * 16 + t2 + 8];
                }
#pragma unroll
                for (int j4 = 0; j4 < 4; j4++)
                    mma16816(sf[jg * 4 + j4], qh[kc], bhf[j4]);
#pragma unroll
                for (int j4 = 0; j4 < 4; j4++)
                    mma16816(sf[jg * 4 + j4], qh[kc], blf[j4]);
#pragma unroll
                for (int j4 = 0; j4 < 4; j4++)
                    mma16816(sf[jg * 4 + j4], ql[kc], bhf[j4]);
            }
        }

        // ---- online softmax ----
        float tm0 = -1e30f, tm1 = -1e30f;
#pragma unroll
        for (int j = 0; j < 8; j++) {
            tm0 = fmaxf(tm0, fmaxf(sf[j][0], sf[j][1]));
            tm1 = fmaxf(tm1, fmaxf(sf[j][2], sf[j][3]));
        }
        tm0 = fmaxf(tm0, __shfl_xor_sync(0xffffffffu, tm0, 1));
        tm0 = fmaxf(tm0, __shfl_xor_sync(0xffffffffu, tm0, 2));
        tm1 = fmaxf(tm1, __shfl_xor_sync(0xffffffffu, tm1, 1));
        tm1 = fmaxf(tm1, __shfl_xor_sync(0xffffffffu, tm1, 2));
        const float mn0 = fmaxf(mr0, tm0);
        const float mn1 = fmaxf(mr1, tm1);
        const float al0 = __expf(mr0 - mn0);
        const float al1 = __expf(mr1 - mn1);
        float rs0 = 0.0f, rs1 = 0.0f;
#pragma unroll
        for (int j = 0; j < 8; j++) {
            sf[j][0] = __expf(sf[j][0] - mn0);
            sf[j][1] = __expf(sf[j][1] - mn0);
            sf[j][2] = __expf(sf[j][2] - mn1);
            sf[j][3] = __expf(sf[j][3] - mn1);
            rs0 += sf[j][0] + sf[j][1];
            rs1 += sf[j][2] + sf[j][3];
        }
        rs0 += __shfl_xor_sync(0xffffffffu, rs0, 1);
        rs0 += __shfl_xor_sync(0xffffffffu, rs0, 2);
        rs1 += __shfl_xor_sync(0xffffffffu, rs1, 1);
        rs1 += __shfl_xor_sync(0xffffffffu, rs1, 2);
        lr0 = lr0 * al0 + rs0;
        lr1 = lr1 * al1 + rs1;
        mr0 = mn0; mr1 = mn1;
#pragma unroll
        for (int j = 0; j < 8; j++) {
            of[j][0] *= al0; of[j][1] *= al0;
            of[j][2] *= al1; of[j][3] *= al1;
        }

        // ---- O += P V (split P in registers; j-groups of 4) ----
#pragma unroll
        for (int kc = 0; kc < 4; kc++) {
            uint32_t pah[4], pal[4];
            split2(sf[2*kc][0],   sf[2*kc][1],   pah[0], pal[0]);
            split2(sf[2*kc][2],   sf[2*kc][3],   pah[1], pal[1]);
            split2(sf[2*kc+1][0], sf[2*kc+1][1], pah[2], pal[2]);
            split2(sf[2*kc+1][2], sf[2*kc+1][3], pah[3], pal[3]);
#pragma unroll
            for (int jg = 0; jg < 2; jg++) {
                uint32_t vhf[4][2], vlf[4][2];
#pragma unroll
                for (int j4 = 0; j4 < 4; j4++) {
                    const int n0 = (jg * 4 + j4) * 8 + g;
                    vhf[j4][0] = *(const uint32_t*)&Vt0[n0 * 72 + kc * 16 + t2];
                    vhf[j4][1] = *(const uint32_t*)&Vt0[n0 * 72 + kc * 16 + t2 + 8];
                    vlf[j4][0] = *(const uint32_t*)&Vt1[n0 * 72 + kc * 16 + t2];
                    vlf[j4][1] = *(const uint32_t*)&Vt1[n0 * 72 + kc * 16 + t2 + 8];
                }
#pragma unroll
                for (int j4 = 0; j4 < 4; j4++)
                    mma16816(of[jg * 4 + j4], pah, vhf[j4]);
#pragma unroll
                for (int j4 = 0; j4 < 4; j4++)
                    mma16816(of[jg * 4 + j4], pah, vlf[j4]);
#pragma unroll
                for (int j4 = 0; j4 < 4; j4++)
                    mma16816(of[jg * 4 + j4], pal, vhf[j4]);
            }
        }

#pragma unroll
        for (int i = 0; i < 16; i++) vcur[i] = vnxt[i];
    }

    // ---- epilogue: normalize, split, store Y ----
    const float inv0 = 1.0f / lr0;
    const float inv1 = 1.0f / lr1;
#pragma unroll
    for (int j = 0; j < 8; j++) {
        uint32_t h0, l0, h1, l1;
        split2(of[j][0] * inv0, of[j][1] * inv0, h0, l0);
        split2(of[j][2] * inv1, of[j][3] * inv1, h1, l1);
        const size_t o0 = (size_t)(m0 + g) * D_ + col0 + j * 8 + t2;
        const size_t o1 = (size_t)(m0 + g + 8) * D_ + col0 + j * 8 + t2;
        *(uint32_t*)&yH[o0] = h0;
        *(uint32_t*)&yL[o0] = l0;
        *(uint32_t*)&yH[o1] = h1;
        *(uint32_t*)&yL[o1] = l1;
    }
}

// ---------------------------------------------------------------------------
// Launch
// ---------------------------------------------------------------------------
extern "C" void kernel_launch(void* const* d_in, const int* in_sizes, int n_in,
                              void* d_out, int out_size)
{
    const float* dec = (const float*)d_in[0];
    const float* enc = (const float*)d_in[1];
    const float* Wq  = (const float*)d_in[2];
    const float* bq  = (const float*)d_in[3];
    const float* Wk  = (const float*)d_in[4];
    const float* bk  = (const float*)d_in[5];
    const float* Wv  = (const float*)d_in[6];
    const float* bv  = (const float*)d_in[7];
    const float* Wp  = (const float*)d_in[8];
    const float* bp  = (const float*)d_in[9];
    float* out = (float*)d_out;

    __nv_bfloat16 *decH,*decL,*encH,*encL;
    __nv_bfloat16 *qHp,*qLp,*kHp,*kLp,*vHp,*vLp,*yHp,*yLp;
    __nv_bfloat16 *wqH,*wqL,*wkH,*wkL,*wvH,*wvL,*wpH,*wpL;
    cudaGetSymbolAddress((void**)&decH, g_decH); cudaGetSymbolAddress((void**)&decL, g_decL);
    cudaGetSymbolAddress((void**)&encH, g_encH); cudaGetSymbolAddress((void**)&encL, g_encL);
    cudaGetSymbolAddress((void**)&qHp, g_qH);   cudaGetSymbolAddress((void**)&qLp, g_qL);
    cudaGetSymbolAddress((void**)&kHp, g_kH);   cudaGetSymbolAddress((void**)&kLp, g_kL);
    cudaGetSymbolAddress((void**)&vHp, g_vH);   cudaGetSymbolAddress((void**)&vLp, g_vL);
    cudaGetSymbolAddress((void**)&yHp, g_yH);   cudaGetSymbolAddress((void**)&yLp, g_yL);
    cudaGetSymbolAddress((void**)&wqH, g_wqH);  cudaGetSymbolAddress((void**)&wqL, g_wqL);
    cudaGetSymbolAddress((void**)&wkH, g_wkH);  cudaGetSymbolAddress((void**)&wkL, g_wkL);
    cudaGetSymbolAddress((void**)&wvH, g_wvH);  cudaGetSymbolAddress((void**)&wvL, g_wvL);
    cudaGetSymbolAddress((void**)&wpH, g_wpH);  cudaGetSymbolAddress((void**)&wpL, g_wpL);

    cudaFuncSetAttribute(gemm_hmma3, cudaFuncAttributeMaxDynamicSharedMemorySize, GSMEM);
    cudaFuncSetAttribute(attn_hmma,  cudaFuncAttributeMaxDynamicSharedMemorySize, AT_SMEM);

    const int nAct4 = M_ * D_ / 4;
    const int nW4   = D_ * D_ / 4;

    split_bf16<<<(nAct4 + 255) / 256, 256>>>(dec, decH, decL, nAct4);
    split_bf16<<<(nAct4 + 255) / 256, 256>>>(enc, encH, encL, nAct4);
    split_bf16<<<(nW4 + 255) / 256, 256>>>(Wq, wqH, wqL, nW4);
    split_bf16<<<(nW4 + 255) / 256, 256>>>(Wk, wkH, wkL, nW4);
    split_bf16<<<(nW4 + 255) / 256, 256>>>(Wv, wvH, wvL, nW4);
    split_bf16<<<(nW4 + 255) / 256, 256>>>(Wp, wpH, wpL, nW4);

    dim3 ggrid(D_ / 128, M_ / 128);
    gemm_hmma3<<<ggrid, 256, GSMEM>>>(decH, decL, wqH, wqL, bq,
                                      nullptr, qHp, qLp, 0.125f);
    gemm_hmma3<<<ggrid, 256, GSMEM>>>(encH, encL, wkH, wkL, bk,
                                      nullptr, kHp, kLp, 1.0f);
    gemm_hmma3<<<ggrid, 256, GSMEM>>>(encH, encL, wvH, wvL, bv,
                                      nullptr, vHp, vLp, 1.0f);

    attn_hmma<<<dim3(S_ / 128, B_ * H_), 256, AT_SMEM>>>(qHp, qLp, kHp, kLp,
                                                         vHp, vLp, yHp, yLp);

    gemm_hmma3<<<ggrid, 256, GSMEM>>>(yHp, yLp, wpH, wpL, bp,
                                      out, nullptr, nullptr, 1.0f);
}

// round 7
// speedup vs baseline: 2.4791x; 1.0552x over previous
#include <cuda_runtime.h>
#include <cuda_bf16.h>
#include <cstdint>

#define B_  2
#define S_  2048
#define D_  1024
#define H_  16
#define HD_ 64
#define M_  (B_*S_)   // 4096

// ---------------------------------------------------------------------------
// Scratch (device globals). All split bf16 pairs.
// ---------------------------------------------------------------------------
__device__ __nv_bfloat16 g_decH[M_*D_], g_decL[M_*D_];
__device__ __nv_bfloat16 g_encH[M_*D_], g_encL[M_*D_];
__device__ __nv_bfloat16 g_qH[M_*D_],   g_qL[M_*D_];
__device__ __nv_bfloat16 g_kH[M_*D_],   g_kL[M_*D_];
__device__ __nv_bfloat16 g_vH[M_*D_],   g_vL[M_*D_];
__device__ __nv_bfloat16 g_yH[M_*D_],   g_yL[M_*D_];
__device__ __nv_bfloat16 g_wqH[D_*D_],  g_wqL[D_*D_];
__device__ __nv_bfloat16 g_wkH[D_*D_],  g_wkL[D_*D_];
__device__ __nv_bfloat16 g_wvH[D_*D_],  g_wvL[D_*D_];
__device__ __nv_bfloat16 g_wpH[D_*D_],  g_wpL[D_*D_];

// ---------------------------------------------------------------------------
// fp32 -> (hi, lo) bf16 splits
// ---------------------------------------------------------------------------
__device__ __forceinline__ void split4_store(const float4 v,
                                             __nv_bfloat16* hi, __nv_bfloat16* lo, int i)
{
    float x[4] = {v.x, v.y, v.z, v.w};
    unsigned short h[4], l[4];
#pragma unroll
    for (int j = 0; j < 4; j++) {
        __nv_bfloat16 hb = __float2bfloat16(x[j]);
        __nv_bfloat16 lb = __float2bfloat16(x[j] - __bfloat162float(hb));
        h[j] = __bfloat16_as_ushort(hb);
        l[j] = __bfloat16_as_ushort(lb);
    }
    uint2 hv, lv;
    hv.x = (uint32_t)h[0] | ((uint32_t)h[1] << 16);
    hv.y = (uint32_t)h[2] | ((uint32_t)h[3] << 16);
    lv.x = (uint32_t)l[0] | ((uint32_t)l[1] << 16);
    lv.y = (uint32_t)l[2] | ((uint32_t)l[3] << 16);
    ((uint2*)hi)[i] = hv;
    ((uint2*)lo)[i] = lv;
}

__global__ __launch_bounds__(256)
void split_bf16(const float* __restrict__ src,
                __nv_bfloat16* __restrict__ hi,
                __nv_bfloat16* __restrict__ lo, int n4)
{
    int i = blockIdx.x * blockDim.x + threadIdx.x;
    if (i >= n4) return;
    split4_store(((const float4*)src)[i], hi, lo, i);
}

// all four weight matrices in one launch (attribution + fewer launches)
#define NW4_ (D_*D_/4)   // 262144 float4 per weight
__global__ __launch_bounds__(256)
void split_w4(const float* __restrict__ W0, const float* __restrict__ W1,
              const float* __restrict__ W2, const float* __restrict__ W3,
              __nv_bfloat16* __restrict__ H0, __nv_bfloat16* __restrict__ L0,
              __nv_bfloat16* __restrict__ H1, __nv_bfloat16* __restrict__ L1,
              __nv_bfloat16* __restrict__ H2, __nv_bfloat16* __restrict__ L2,
              __nv_bfloat16* __restrict__ H3, __nv_bfloat16* __restrict__ L3)
{
    int i = blockIdx.x * blockDim.x + threadIdx.x;   // 0 .. 4*NW4_-1
    int which = i >> 18;                              // NW4_ = 2^18
    int idx   = i & (NW4_ - 1);
    const float* src; __nv_bfloat16 *hi, *lo;
    switch (which) {
        case 0:  src = W0; hi = H0; lo = L0; break;
        case 1:  src = W1; hi = H1; lo = L1; break;
        case 2:  src = W2; hi = H2; lo = L2; break;
        default: src = W3; hi = H3; lo = L3; break;
    }
    split4_store(((const float4*)src)[idx], hi, lo, idx);
}

// ---------------------------------------------------------------------------
// Helpers (baseline PTX only)
// ---------------------------------------------------------------------------
__device__ __forceinline__ uint32_t smem_u32(const void* p) {
    uint32_t a;
    asm("{ .reg .u64 t; cvta.to.shared.u64 t, %1; cvt.u32.u64 %0, t; }"
        : "=r"(a) : "l"(p));
    return a;
}

__device__ __forceinline__ void mma16816(float* c, const uint32_t* a, const uint32_t* b) {
    asm volatile(
        "mma.sync.aligned.m16n8k16.row.col.f32.bf16.bf16.f32 "
        "{%0,%1,%2,%3}, {%4,%5,%6,%7}, {%8,%9}, {%0,%1,%2,%3};"
        : "+f"(c[0]), "+f"(c[1]), "+f"(c[2]), "+f"(c[3])
        : "r"(a[0]), "r"(a[1]), "r"(a[2]), "r"(a[3]), "r"(b[0]), "r"(b[1]));
}

__device__ __forceinline__ void ldsm4(uint32_t& r0, uint32_t& r1,
                                      uint32_t& r2, uint32_t& r3, uint32_t addr) {
    asm volatile("ldmatrix.sync.aligned.m8n8.x4.shared.b16 {%0,%1,%2,%3}, [%4];"
                 : "=r"(r0), "=r"(r1), "=r"(r2), "=r"(r3) : "r"(addr));
}

__device__ __forceinline__ void cp_async16(uint32_t dst, const void* src) {
    asm volatile("cp.async.cg.shared.global [%0], [%1], 16;\n"
                 :: "r"(dst), "l"(src) : "memory");
}
__device__ __forceinline__ void cp_commit() {
    asm volatile("cp.async.commit_group;\n" ::: "memory");
}
__device__ __forceinline__ void cp_wait1() {
    asm volatile("cp.async.wait_group 1;\n" ::: "memory");
}
__device__ __forceinline__ void cp_wait0() {
    asm volatile("cp.async.wait_group 0;\n" ::: "memory");
}

__device__ __forceinline__ void split2(float x, float y, uint32_t& hi, uint32_t& lo) {
    __nv_bfloat16 xh = __float2bfloat16(x);
    __nv_bfloat16 yh = __float2bfloat16(y);
    __nv_bfloat16 xl = __float2bfloat16(x - __bfloat162float(xh));
    __nv_bfloat16 yl = __float2bfloat16(y - __bfloat162float(yh));
    __nv_bfloat162 hv; hv.x = xh; hv.y = yh;
    __nv_bfloat162 lv; lv.x = xl; lv.y = yl;
    hi = *(uint32_t*)&hv; lo = *(uint32_t*)&lv;
}

// ---------------------------------------------------------------------------
// bf16x3 split GEMM, ldmatrix fragment path, 2 CTAs/SM.
// CTA 128x128, 8 warps (2m x 4n), warp tile 64x32, K staged 32, double buffer.
// ---------------------------------------------------------------------------
#define KSTEP    32
#define NSTAGE   (D_ / KSTEP)
#define ROWH     40
#define ARRB     (128 * ROWH * 2)
#define STAGEB   (4 * ARRB)
#define GSMEM    (2 * STAGEB)           // 81920

__global__ __launch_bounds__(256, 2)
void gemm_hmma3(const __nv_bfloat16* __restrict__ Ah, const __nv_bfloat16* __restrict__ Al,
                const __nv_bfloat16* __restrict__ Wh, const __nv_bfloat16* __restrict__ Wl,
                const float* __restrict__ bias,
                float* __restrict__ CF,
                __nv_bfloat16* __restrict__ CH, __nv_bfloat16* __restrict__ CL,
                float scale)
{
    extern __shared__ __align__(16) uint16_t sm[];

    const int tid  = threadIdx.x;
    const int wid  = tid >> 5;
    const int lane = tid & 31;
    const int g    = lane >> 2;
    const int t2   = (lane & 3) * 2;
    const int wm   = wid >> 2;
    const int wn   = wid & 3;
    const int bn   = blockIdx.x * 128;
    const int bm   = blockIdx.y * 128;

    // ldmatrix lane-address components
    const int lr   = lane & 7;
    const int lrow = lr + 8 * ((lane >> 3) & 1);   // A row offset
    const int lkh  = 8 * ((lane >> 4) & 1);        // A k offset
    const int brow = lr + 8 * ((lane >> 4) & 1);   // B row offset
    const int bk   = 8 * ((lane >> 3) & 1);        // B k offset

    const uint32_t smb = smem_u32(sm);

    auto load_stage = [&](int s) {
        const int buf = s & 1;
        const int k0  = s * KSTEP;
        const uint32_t base = smb + buf * STAGEB;
#pragma unroll
        for (int i = 0; i < 2; i++) {
            const int c   = i * 256 + tid;     // 0..511
            const int row = c >> 2;
            const int q   = c & 3;
            const uint32_t off = row * (ROWH * 2) + q * 16;
            const size_t gofA = (size_t)(bm + row) * D_ + k0 + q * 8;
            const size_t gofW = (size_t)(bn + row) * D_ + k0 + q * 8;
            cp_async16(base + off,            Ah + gofA);
            cp_async16(base + ARRB + off,     Al + gofA);
            cp_async16(base + 2 * ARRB + off, Wh + gofW);
            cp_async16(base + 3 * ARRB + off, Wl + gofW);
        }
        cp_commit();
    };

    float acc[4][4][4];
#pragma unroll
    for (int mi = 0; mi < 4; mi++)
#pragma unroll
        for (int nj = 0; nj < 4; nj++)
#pragma unroll
            for (int r = 0; r < 4; r++) acc[mi][nj][r] = 0.0f;

    load_stage(0);
    load_stage(1);

    for (int s = 0; s < NSTAGE; s++) {
        const int buf = s & 1;
        if (s < NSTAGE - 1) cp_wait1(); else cp_wait0();
        __syncthreads();

        const uint32_t sb = smb + buf * STAGEB;

#pragma unroll
        for (int ks = 0; ks < 2; ks++) {
            const int ko = ks * 16;
            uint32_t ah[4][4], al[4][4], bh[4][2], bl[4][2];

            const uint32_t aA = sb + ((wm * 64 + lrow) * ROWH + ko + lkh) * 2;
#pragma unroll
            for (int mi = 0; mi < 4; mi++)
                ldsm4(ah[mi][0], ah[mi][1], ah[mi][2], ah[mi][3],
                      aA + mi * (16 * ROWH * 2));
#pragma unroll
            for (int mi = 0; mi < 4; mi++)
                ldsm4(al[mi][0], al[mi][1], al[mi][2], al[mi][3],
                      aA + ARRB + mi * (16 * ROWH * 2));

            const uint32_t bB = sb + 2 * ARRB
                              + ((wn * 32 + brow) * ROWH + ko + bk) * 2;
            ldsm4(bh[0][0], bh[0][1], bh[1][0], bh[1][1], bB);
            ldsm4(bh[2][0], bh[2][1], bh[3][0], bh[3][1], bB + 16 * ROWH * 2);
            ldsm4(bl[0][0], bl[0][1], bl[1][0], bl[1][1], bB + ARRB);
            ldsm4(bl[2][0], bl[2][1], bl[3][0], bl[3][1], bB + ARRB + 16 * ROWH * 2);

#pragma unroll
            for (int mi = 0; mi < 4; mi++)
#pragma unroll
                for (int nj = 0; nj < 4; nj++)
                    mma16816(acc[mi][nj], ah[mi], bh[nj]);
#pragma unroll
            for (int mi = 0; mi < 4; mi++)
#pragma unroll
                for (int nj = 0; nj < 4; nj++)
                    mma16816(acc[mi][nj], ah[mi], bl[nj]);
#pragma unroll
            for (int mi = 0; mi < 4; mi++)
#pragma unroll
                for (int nj = 0; nj < 4; nj++)
                    mma16816(acc[mi][nj], al[mi], bh[nj]);
        }
        __syncthreads();
        if (s + 2 < NSTAGE) load_stage(s + 2);
    }

    // ---- epilogue ----
#pragma unroll
    for (int mi = 0; mi < 4; mi++) {
        const int r0 = bm + wm * 64 + mi * 16 + g;
#pragma unroll
        for (int nj = 0; nj < 4; nj++) {
            const int c0 = bn + wn * 32 + nj * 8 + t2;
            const float b0 = bias[c0], b1 = bias[c0 + 1];
            float v00 = acc[mi][nj][0] + b0, v01 = acc[mi][nj][1] + b1;
            float v10 = acc[mi][nj][2] + b0, v11 = acc[mi][nj][3] + b1;
            if (CF) {
                *(float2*)&CF[(size_t)r0 * D_ + c0]       = make_float2(v00, v01);
                *(float2*)&CF[(size_t)(r0 + 8) * D_ + c0] = make_float2(v10, v11);
            } else {
                uint32_t h0, l0, h1, l1;
                split2(v00 * scale, v01 * scale, h0, l0);
                split2(v10 * scale, v11 * scale, h1, l1);
                *(uint32_t*)&CH[(size_t)r0 * D_ + c0]       = h0;
                *(uint32_t*)&CL[(size_t)r0 * D_ + c0]       = l0;
                *(uint32_t*)&CH[(size_t)(r0 + 8) * D_ + c0] = h1;
                *(uint32_t*)&CL[(size_t)(r0 + 8) * D_ + c0] = l1;
            }
        }
    }
}

// ---------------------------------------------------------------------------
// Pipelined HMMA flash-attention (unchanged from round 5 — 1036us passing).
// ---------------------------------------------------------------------------
#define AT_ARR   4608
#define AT_SMEM  (8 * AT_ARR * 2)
#define NTILE_   (S_ / 64)

__global__ __launch_bounds__(256)
void attn_hmma(const __nv_bfloat16* __restrict__ qH, const __nv_bfloat16* __restrict__ qL,
               const __nv_bfloat16* __restrict__ kH, const __nv_bfloat16* __restrict__ kL,
               const __nv_bfloat16* __restrict__ vH, const __nv_bfloat16* __restrict__ vL,
               __nv_bfloat16* __restrict__ yH, __nv_bfloat16* __restrict__ yL)
{
    extern __shared__ __align__(16) uint16_t sm[];
    const int tid  = threadIdx.x;
    const int wid  = tid >> 5;
    const int lane = tid & 31;
    const int g    = lane >> 2;
    const int t2   = (lane & 3) * 2;
    const int q0   = blockIdx.x * 128;
    const int bh   = blockIdx.y;
    const int b    = bh >> 4;
    const int h    = bh & 15;
    const int col0 = h * HD_;
    const int m0   = b * S_ + q0 + wid * 16;

    uint32_t qh[4][4], ql[4][4];
    {
        const __nv_bfloat16* r0h = qH + (size_t)(m0 + g) * D_ + col0;
        const __nv_bfloat16* r1h = qH + (size_t)(m0 + g + 8) * D_ + col0;
        const __nv_bfloat16* r0l = qL + (size_t)(m0 + g) * D_ + col0;
        const __nv_bfloat16* r1l = qL + (size_t)(m0 + g + 8) * D_ + col0;
#pragma unroll
        for (int kc = 0; kc < 4; kc++) {
            qh[kc][0] = *(const uint32_t*)(r0h + kc * 16 + t2);
            qh[kc][1] = *(const uint32_t*)(r1h + kc * 16 + t2);
            qh[kc][2] = *(const uint32_t*)(r0h + kc * 16 + t2 + 8);
            qh[kc][3] = *(const uint32_t*)(r1h + kc * 16 + t2 + 8);
            ql[kc][0] = *(const uint32_t*)(r0l + kc * 16 + t2);
            ql[kc][1] = *(const uint32_t*)(r1l + kc * 16 + t2);
            ql[kc][2] = *(const uint32_t*)(r0l + kc * 16 + t2 + 8);
            ql[kc][3] = *(const uint32_t*)(r1l + kc * 16 + t2 + 8);
        }
    }

    const uint32_t smb = smem_u32(sm);
    auto loadK = [&](int kb, int buf) {
#pragma unroll
        for (int i = 0; i < 4; i++) {
            int c = i * 256 + tid;
            int a = c >> 9;
            int idx = c & 511;
            int row = idx >> 3, qq = idx & 7;
            uint32_t dst = smb + ((buf * 2 + a) * AT_ARR + row * 72 + qq * 8) * 2;
            const __nv_bfloat16* src = (a ? kL : kH)
                + (size_t)(b * S_ + kb + row) * D_ + col0 + qq * 8;
            cp_async16(dst, src);
        }
        cp_commit();
    };
    auto loadV = [&](int kb, uint32_t* vr) {
#pragma unroll
        for (int i = 0; i < 16; i++) {
            int u = i * 256 + tid;
            int a = u >> 11;
            int v = u & 2047;
            int key = v & 63, dpi = v >> 6;
            vr[i] = *(const uint32_t*)((a ? vL : vH)
                + (size_t)(b * S_ + kb + key) * D_ + col0 + dpi * 2);
        }
    };
    auto stsV = [&](int buf, const uint32_t* vr) {
#pragma unroll
        for (int i = 0; i < 16; i++) {
            int u = i * 256 + tid;
            int a = u >> 11;
            int v = u & 2047;
            int key = v & 63, dpi = v >> 6;
            uint16_t* dst = sm + (4 + buf * 2 + a) * AT_ARR;
            dst[(2 * dpi)     * 72 + key] = (uint16_t)(vr[i] & 0xffff);
            dst[(2 * dpi + 1) * 72 + key] = (uint16_t)(vr[i] >> 16);
        }
    };

    float of[8][4];
#pragma unroll
    for (int j = 0; j < 8; j++)
#pragma unroll
        for (int r = 0; r < 4; r++) of[j][r] = 0.0f;
    float mr0 = -1e30f, mr1 = -1e30f, lr0 = 0.0f, lr1 = 0.0f;

    uint32_t vcur[16], vnxt[16];
    loadK(0, 0);
    loadV(0, vcur);

    for (int it = 0; it < NTILE_; it++) {
        const int buf = it & 1;
        cp_wait0();
        stsV(buf, vcur);
        __syncthreads();
        if (it + 1 < NTILE_) {
            loadK((it + 1) * 64, buf ^ 1);
            loadV((it + 1) * 64, vnxt);
        }

        const uint16_t* Ks0 = sm + (buf * 2 + 0) * AT_ARR;
        const uint16_t* Ks1 = sm + (buf * 2 + 1) * AT_ARR;
        const uint16_t* Vt0 = sm + (4 + buf * 2 + 0) * AT_ARR;
        const uint16_t* Vt1 = sm + (4 + buf * 2 + 1) * AT_ARR;

        float sf[8][4];
#pragma unroll
        for (int j = 0; j < 8; j++)
#pragma unroll
            for (int r = 0; r < 4; r++) sf[j][r] = 0.0f;

#pragma unroll
        for (int kc = 0; kc < 4; kc++) {
#pragma unroll
            for (int jg = 0; jg < 2; jg++) {
                uint32_t bhf[4][2], blf[4][2];
#pragma unroll
                for (int j4 = 0; j4 < 4; j4++) {
                    const int n0 = (jg * 4 + j4) * 8 + g;
                    bhf[j4][0] = *(const uint32_t*)&Ks0[n0 * 72 + kc * 16 + t2];
                    bhf[j4][1] = *(const uint32_t*)&Ks0[n0 * 72 + kc * 16 + t2 + 8];
                    blf[j4][0] = *(const uint32_t*)&Ks1[n0 * 72 + kc * 16 + t2];
                    blf[j4][1] = *(const uint32_t*)&Ks1[n0 * 72 + kc * 16 + t2 + 8];
                }
#pragma unroll
                for (int j4 = 0; j4 < 4; j4++)
                    mma16816(sf[jg * 4 + j4], qh[kc], bhf[j4]);
#pragma unroll
                for (int j4 = 0; j4 < 4; j4++)
                    mma16816(sf[jg * 4 + j4], qh[kc], blf[j4]);
#pragma unroll
                for (int j4 = 0; j4 < 4; j4++)
                    mma16816(sf[jg * 4 + j4], ql[kc], bhf[j4]);
            }
        }

        float tm0 = -1e30f, tm1 = -1e30f;
#pragma unroll
        for (int j = 0; j < 8; j++) {
            tm0 = fmaxf(tm0, fmaxf(sf[j][0], sf[j][1]));
            tm1 = fmaxf(tm1, fmaxf(sf[j][2], sf[j][3]));
        }
        tm0 = fmaxf(tm0, __shfl_xor_sync(0xffffffffu, tm0, 1));
        tm0 = fmaxf(tm0, __shfl_xor_sync(0xffffffffu, tm0, 2));
        tm1 = fmaxf(tm1, __shfl_xor_sync(0xffffffffu, tm1, 1));
        tm1 = fmaxf(tm1, __shfl_xor_sync(0xffffffffu, tm1, 2));
        const float mn0 = fmaxf(mr0, tm0);
        const float mn1 = fmaxf(mr1, tm1);
        const float al0 = __expf(mr0 - mn0);
        const float al1 = __expf(mr1 - mn1);
        float rs0 = 0.0f, rs1 = 0.0f;
#pragma unroll
        for (int j = 0; j < 8; j++) {
            sf[j][0] = __expf(sf[j][0] - mn0);
            sf[j][1] = __expf(sf[j][1] - mn0);
            sf[j][2] = __expf(sf[j][2] - mn1);
            sf[j][3] = __expf(sf[j][3] - mn1);
            rs0 += sf[j][0] + sf[j][1];
            rs1 += sf[j][2] + sf[j][3];
        }
        rs0 += __shfl_xor_sync(0xffffffffu, rs0, 1);
        rs0 += __shfl_xor_sync(0xffffffffu, rs0, 2);
        rs1 += __shfl_xor_sync(0xffffffffu, rs1, 1);
        rs1 += __shfl_xor_sync(0xffffffffu, rs1, 2);
        lr0 = lr0 * al0 + rs0;
        lr1 = lr1 * al1 + rs1;
        mr0 = mn0; mr1 = mn1;
#pragma unroll
        for (int j = 0; j < 8; j++) {
            of[j][0] *= al0; of[j][1] *= al0;
            of[j][2] *= al1; of[j][3] *= al1;
        }

#pragma unroll
        for (int kc = 0; kc < 4; kc++) {
            uint32_t pah[4], pal[4];
            split2(sf[2*kc][0],   sf[2*kc][1],   pah[0], pal[0]);
            split2(sf[2*kc][2],   sf[2*kc][3],   pah[1], pal[1]);
            split2(sf[2*kc+1][0], sf[2*kc+1][1], pah[2], pal[2]);
            split2(sf[2*kc+1][2], sf[2*kc+1][3], pah[3], pal[3]);
#pragma unroll
            for (int jg = 0; jg < 2; jg++) {
                uint32_t vhf[4][2], vlf[4][2];
#pragma unroll
                for (int j4 = 0; j4 < 4; j4++) {
                    const int n0 = (jg * 4 + j4) * 8 + g;
                    vhf[j4][0] = *(const uint32_t*)&Vt0[n0 * 72 + kc * 16 + t2];
                    vhf[j4][1] = *(const uint32_t*)&Vt0[n0 * 72 + kc * 16 + t2 + 8];
                    vlf[j4][0] = *(const uint32_t*)&Vt1[n0 * 72 + kc * 16 + t2];
                    vlf[j4][1] = *(const uint32_t*)&Vt1[n0 * 72 + kc * 16 + t2 + 8];
                }
#pragma unroll
                for (int j4 = 0; j4 < 4; j4++)
                    mma16816(of[jg * 4 + j4], pah, vhf[j4]);
#pragma unroll
                for (int j4 = 0; j4 < 4; j4++)
                    mma16816(of[jg * 4 + j4], pah, vlf[j4]);
#pragma unroll
                for (int j4 = 0; j4 < 4; j4++)
                    mma16816(of[jg * 4 + j4], pal, vhf[j4]);
            }
        }

#pragma unroll
        for (int i = 0; i < 16; i++) vcur[i] = vnxt[i];
    }

    const float inv0 = 1.0f / lr0;
    const float inv1 = 1.0f / lr1;
#pragma unroll
    for (int j = 0; j < 8; j++) {
        uint32_t h0, l0, h1, l1;
        split2(of[j][0] * inv0, of[j][1] * inv0, h0, l0);
        split2(of[j][2] * inv1, of[j][3] * inv1, h1, l1);
        const size_t o0 = (size_t)(m0 + g) * D_ + col0 + j * 8 + t2;
        const size_t o1 = (size_t)(m0 + g + 8) * D_ + col0 + j * 8 + t2;
        *(uint32_t*)&yH[o0] = h0;
        *(uint32_t*)&yL[o0] = l0;
        *(uint32_t*)&yH[o1] = h1;
        *(uint32_t*)&yL[o1] = l1;
    }
}

// ---------------------------------------------------------------------------
// Launch. Order matters for ncu -s 5 -c 1: the 6th launch is gemmV.
// ---------------------------------------------------------------------------
extern "C" void kernel_launch(void* const* d_in, const int* in_sizes, int n_in,
                              void* d_out, int out_size)
{
    const float* dec = (const float*)d_in[0];
    const float* enc = (const float*)d_in[1];
    const float* Wq  = (const float*)d_in[2];
    const float* bq  = (const float*)d_in[3];
    const float* Wk  = (const float*)d_in[4];
    const float* bk  = (const float*)d_in[5];
    const float* Wv  = (const float*)d_in[6];
    const float* bv  = (const float*)d_in[7];
    const float* Wp  = (const float*)d_in[8];
    const float* bp  = (const float*)d_in[9];
    float* out = (float*)d_out;

    __nv_bfloat16 *decH,*decL,*encH,*encL;
    __nv_bfloat16 *qHp,*qLp,*kHp,*kLp,*vHp,*vLp,*yHp,*yLp;
    __nv_bfloat16 *wqH,*wqL,*wkH,*wkL,*wvH,*wvL,*wpH,*wpL;
    cudaGetSymbolAddress((void**)&decH, g_decH); cudaGetSymbolAddress((void**)&decL, g_decL);
    cudaGetSymbolAddress((void**)&encH, g_encH); cudaGetSymbolAddress((void**)&encL, g_encL);
    cudaGetSymbolAddress((void**)&qHp, g_qH);   cudaGetSymbolAddress((void**)&qLp, g_qL);
    cudaGetSymbolAddress((void**)&kHp, g_kH);   cudaGetSymbolAddress((void**)&kLp, g_kL);
    cudaGetSymbolAddress((void**)&vHp, g_vH);   cudaGetSymbolAddress((void**)&vLp, g_vL);
    cudaGetSymbolAddress((void**)&yHp, g_yH);   cudaGetSymbolAddress((void**)&yLp, g_yL);
    cudaGetSymbolAddress((void**)&wqH, g_wqH);  cudaGetSymbolAddress((void**)&wqL, g_wqL);
    cudaGetSymbolAddress((void**)&wkH, g_wkH);  cudaGetSymbolAddress((void**)&wkL, g_wkL);
    cudaGetSymbolAddress((void**)&wvH, g_wvH);  cudaGetSymbolAddress((void**)&wvL, g_wvL);
    cudaGetSymbolAddress((void**)&wpH, g_wpH);  cudaGetSymbolAddress((void**)&wpL, g_wpL);

    cudaFuncSetAttribute(gemm_hmma3, cudaFuncAttributeMaxDynamicSharedMemorySize, GSMEM);
    cudaFuncSetAttribute(attn_hmma,  cudaFuncAttributeMaxDynamicSharedMemorySize, AT_SMEM);

    const int nAct4 = M_ * D_ / 4;

    // 1,2: activation splits; 3: all weight splits
    split_bf16<<<(nAct4 + 255) / 256, 256>>>(dec, decH, decL, nAct4);
    split_bf16<<<(nAct4 + 255) / 256, 256>>>(enc, encH, encL, nAct4);
    split_w4<<<(4 * NW4_ + 255) / 256, 256>>>(Wq, Wk, Wv, Wp,
                                              wqH, wqL, wkH, wkL,
                                              wvH, wvL, wpH, wpL);

    dim3 ggrid(D_ / 128, M_ / 128);
    // 4,5,6: projections (6th launch = gemmV -> ncu capture target)
    gemm_hmma3<<<ggrid, 256, GSMEM>>>(decH, decL, wqH, wqL, bq,
                                      nullptr, qHp, qLp, 0.125f);
    gemm_hmma3<<<ggrid, 256, GSMEM>>>(encH, encL, wkH, wkL, bk,
                                      nullptr, kHp, kLp, 1.0f);
    gemm_hmma3<<<ggrid, 256, GSMEM>>>(encH, encL, wvH, wvL, bv,
                                      nullptr, vHp, vLp, 1.0f);

    // 7: attention
    attn_hmma<<<dim3(S_ / 128, B_ * H_), 256, AT_SMEM>>>(qHp, qLp, kHp, kLp,
                                                         vHp, vLp, yHp, yLp);

    // 8: output projection
    gemm_hmma3<<<ggrid, 256, GSMEM>>>(yHp, yLp, wpH, wpL, bp,
                                      out, nullptr, nullptr, 1.0f);
}

// round 9
// speedup vs baseline: 3.6540x; 1.4739x over previous
#include <cuda_runtime.h>
#include <cuda_bf16.h>
#include <cstdint>

#define B_  2
#define S_  2048
#define D_  1024
#define H_  16
#define HD_ 64
#define M_  (B_*S_)   // 4096

// ---------------------------------------------------------------------------
// Scratch (device globals). All split bf16 pairs.
// ---------------------------------------------------------------------------
__device__ __nv_bfloat16 g_decH[M_*D_], g_decL[M_*D_];
__device__ __nv_bfloat16 g_encH[M_*D_], g_encL[M_*D_];
__device__ __nv_bfloat16 g_qH[M_*D_],   g_qL[M_*D_];
__device__ __nv_bfloat16 g_kH[M_*D_],   g_kL[M_*D_];
__device__ __nv_bfloat16 g_vH[M_*D_],   g_vL[M_*D_];
__device__ __nv_bfloat16 g_yH[M_*D_],   g_yL[M_*D_];
__device__ __nv_bfloat16 g_wqH[D_*D_],  g_wqL[D_*D_];
__device__ __nv_bfloat16 g_wkH[D_*D_],  g_wkL[D_*D_];
__device__ __nv_bfloat16 g_wvH[D_*D_],  g_wvL[D_*D_];
__device__ __nv_bfloat16 g_wpH[D_*D_],  g_wpL[D_*D_];

// ---------------------------------------------------------------------------
// fp32 -> (hi, lo) bf16 splits
// ---------------------------------------------------------------------------
__device__ __forceinline__ void split4_store(const float4 v,
                                             __nv_bfloat16* hi, __nv_bfloat16* lo, int i)
{
    float x[4] = {v.x, v.y, v.z, v.w};
    unsigned short h[4], l[4];
#pragma unroll
    for (int j = 0; j < 4; j++) {
        __nv_bfloat16 hb = __float2bfloat16(x[j]);
        __nv_bfloat16 lb = __float2bfloat16(x[j] - __bfloat162float(hb));
        h[j] = __bfloat16_as_ushort(hb);
        l[j] = __bfloat16_as_ushort(lb);
    }
    uint2 hv, lv;
    hv.x = (uint32_t)h[0] | ((uint32_t)h[1] << 16);
    hv.y = (uint32_t)h[2] | ((uint32_t)h[3] << 16);
    lv.x = (uint32_t)l[0] | ((uint32_t)l[1] << 16);
    lv.y = (uint32_t)l[2] | ((uint32_t)l[3] << 16);
    ((uint2*)hi)[i] = hv;
    ((uint2*)lo)[i] = lv;
}

#define NACT4_ (M_*D_/4)   // 1048576 float4 per activation
__global__ __launch_bounds__(256)
void split_act2(const float* __restrict__ A0, const float* __restrict__ A1,
                __nv_bfloat16* __restrict__ H0, __nv_bfloat16* __restrict__ L0,
                __nv_bfloat16* __restrict__ H1, __nv_bfloat16* __restrict__ L1)
{
    int i = blockIdx.x * blockDim.x + threadIdx.x;    // 0 .. 2*NACT4_-1
    int which = i >> 20;                               // NACT4_ = 2^20
    int idx   = i & (NACT4_ - 1);
    if (which == 0) split4_store(((const float4*)A0)[idx], H0, L0, idx);
    else            split4_store(((const float4*)A1)[idx], H1, L1, idx);
}

#define NW4_ (D_*D_/4)   // 262144 float4 per weight
__global__ __launch_bounds__(256)
void split_w4(const float* __restrict__ W0, const float* __restrict__ W1,
              const float* __restrict__ W2, const float* __restrict__ W3,
              __nv_bfloat16* __restrict__ H0, __nv_bfloat16* __restrict__ L0,
              __nv_bfloat16* __restrict__ H1, __nv_bfloat16* __restrict__ L1,
              __nv_bfloat16* __restrict__ H2, __nv_bfloat16* __restrict__ L2,
              __nv_bfloat16* __restrict__ H3, __nv_bfloat16* __restrict__ L3)
{
    int i = blockIdx.x * blockDim.x + threadIdx.x;
    int which = i >> 18;
    int idx   = i & (NW4_ - 1);
    const float* src; __nv_bfloat16 *hi, *lo;
    switch (which) {
        case 0:  src = W0; hi = H0; lo = L0; break;
        case 1:  src = W1; hi = H1; lo = L1; break;
        case 2:  src = W2; hi = H2; lo = L2; break;
        default: src = W3; hi = H3; lo = L3; break;
    }
    split4_store(((const float4*)src)[idx], hi, lo, idx);
}

// ---------------------------------------------------------------------------
// Helpers (baseline PTX only)
// ---------------------------------------------------------------------------
__device__ __forceinline__ uint32_t smem_u32(const void* p) {
    uint32_t a;
    asm("{ .reg .u64 t; cvta.to.shared.u64 t, %1; cvt.u32.u64 %0, t; }"
        : "=r"(a) : "l"(p));
    return a;
}

__device__ __forceinline__ void mma16816(float* c, const uint32_t* a, const uint32_t* b) {
    asm volatile(
        "mma.sync.aligned.m16n8k16.row.col.f32.bf16.bf16.f32 "
        "{%0,%1,%2,%3}, {%4,%5,%6,%7}, {%8,%9}, {%0,%1,%2,%3};"
        : "+f"(c[0]), "+f"(c[1]), "+f"(c[2]), "+f"(c[3])
        : "r"(a[0]), "r"(a[1]), "r"(a[2]), "r"(a[3]), "r"(b[0]), "r"(b[1]));
}

__device__ __forceinline__ void ldsm4(uint32_t& r0, uint32_t& r1,
                                      uint32_t& r2, uint32_t& r3, uint32_t addr) {
    asm volatile("ldmatrix.sync.aligned.m8n8.x4.shared.b16 {%0,%1,%2,%3}, [%4];"
                 : "=r"(r0), "=r"(r1), "=r"(r2), "=r"(r3) : "r"(addr));
}
__device__ __forceinline__ void ldsm4t(uint32_t& r0, uint32_t& r1,
                                       uint32_t& r2, uint32_t& r3, uint32_t addr) {
    asm volatile("ldmatrix.sync.aligned.m8n8.x4.trans.shared.b16 {%0,%1,%2,%3}, [%4];"
                 : "=r"(r0), "=r"(r1), "=r"(r2), "=r"(r3) : "r"(addr));
}

__device__ __forceinline__ void cp_async16(uint32_t dst, const void* src) {
    asm volatile("cp.async.cg.shared.global [%0], [%1], 16;\n"
                 :: "r"(dst), "l"(src) : "memory");
}
__device__ __forceinline__ void cp_commit() {
    asm volatile("cp.async.commit_group;\n" ::: "memory");
}
__device__ __forceinline__ void cp_wait1() {
    asm volatile("cp.async.wait_group 1;\n" ::: "memory");
}
__device__ __forceinline__ void cp_wait0() {
    asm volatile("cp.async.wait_group 0;\n" ::: "memory");
}

__device__ __forceinline__ void split2(float x, float y, uint32_t& hi, uint32_t& lo) {
    __nv_bfloat16 xh = __float2bfloat16(x);
    __nv_bfloat16 yh = __float2bfloat16(y);
    __nv_bfloat16 xl = __float2bfloat16(x - __bfloat162float(xh));
    __nv_bfloat16 yl = __float2bfloat16(y - __bfloat162float(yh));
    __nv_bfloat162 hv; hv.x = xh; hv.y = yh;
    __nv_bfloat162 lv; lv.x = xl; lv.y = yl;
    hi = *(uint32_t*)&hv; lo = *(uint32_t*)&lv;
}

// ---------------------------------------------------------------------------
// bf16x3 split GEMM (unchanged from round 6 — 87.9us/launch measured).
// ---------------------------------------------------------------------------
#define KSTEP    32
#define NSTAGE   (D_ / KSTEP)
#define ROWH     40
#define ARRB     (128 * ROWH * 2)
#define STAGEB   (4 * ARRB)
#define GSMEM    (2 * STAGEB)

__global__ __launch_bounds__(256, 2)
void gemm_hmma3(const __nv_bfloat16* __restrict__ Ah, const __nv_bfloat16* __restrict__ Al,
                const __nv_bfloat16* __restrict__ Wh, const __nv_bfloat16* __restrict__ Wl,
                const float* __restrict__ bias,
                float* __restrict__ CF,
                __nv_bfloat16* __restrict__ CH, __nv_bfloat16* __restrict__ CL,
                float scale)
{
    extern __shared__ __align__(16) uint16_t sm[];

    const int tid  = threadIdx.x;
    const int wid  = tid >> 5;
    const int lane = tid & 31;
    const int g    = lane >> 2;
    const int t2   = (lane & 3) * 2;
    const int wm   = wid >> 2;
    const int wn   = wid & 3;
    const int bn   = blockIdx.x * 128;
    const int bm   = blockIdx.y * 128;

    const int lr   = lane & 7;
    const int lrow = lr + 8 * ((lane >> 3) & 1);
    const int lkh  = 8 * ((lane >> 4) & 1);
    const int brow = lr + 8 * ((lane >> 4) & 1);
    const int bk   = 8 * ((lane >> 3) & 1);

    const uint32_t smb = smem_u32(sm);

    auto load_stage = [&](int s) {
        const int buf = s & 1;
        const int k0  = s * KSTEP;
        const uint32_t base = smb + buf * STAGEB;
#pragma unroll
        for (int i = 0; i < 2; i++) {
            const int c   = i * 256 + tid;
            const int row = c >> 2;
            const int q   = c & 3;
            const uint32_t off = row * (ROWH * 2) + q * 16;
            const size_t gofA = (size_t)(bm + row) * D_ + k0 + q * 8;
            const size_t gofW = (size_t)(bn + row) * D_ + k0 + q * 8;
            cp_async16(base + off,            Ah + gofA);
            cp_async16(base + ARRB + off,     Al + gofA);
            cp_async16(base + 2 * ARRB + off, Wh + gofW);
            cp_async16(base + 3 * ARRB + off, Wl + gofW);
        }
        cp_commit();
    };

    float acc[4][4][4];
#pragma unroll
    for (int mi = 0; mi < 4; mi++)
#pragma unroll
        for (int nj = 0; nj < 4; nj++)
#pragma unroll
            for (int r = 0; r < 4; r++) acc[mi][nj][r] = 0.0f;

    load_stage(0);
    load_stage(1);

    for (int s = 0; s < NSTAGE; s++) {
        const int buf = s & 1;
        if (s < NSTAGE - 1) cp_wait1(); else cp_wait0();
        __syncthreads();

        const uint32_t sb = smb + buf * STAGEB;

#pragma unroll
        for (int ks = 0; ks < 2; ks++) {
            const int ko = ks * 16;
            uint32_t ah[4][4], al[4][4], bh[4][2], bl[4][2];

            const uint32_t aA = sb + ((wm * 64 + lrow) * ROWH + ko + lkh) * 2;
#pragma unroll
            for (int mi = 0; mi < 4; mi++)
                ldsm4(ah[mi][0], ah[mi][1], ah[mi][2], ah[mi][3],
                      aA + mi * (16 * ROWH * 2));
#pragma unroll
            for (int mi = 0; mi < 4; mi++)
                ldsm4(al[mi][0], al[mi][1], al[mi][2], al[mi][3],
                      aA + ARRB + mi * (16 * ROWH * 2));

            const uint32_t bB = sb + 2 * ARRB
                              + ((wn * 32 + brow) * ROWH + ko + bk) * 2;
            ldsm4(bh[0][0], bh[0][1], bh[1][0], bh[1][1], bB);
            ldsm4(bh[2][0], bh[2][1], bh[3][0], bh[3][1], bB + 16 * ROWH * 2);
            ldsm4(bl[0][0], bl[0][1], bl[1][0], bl[1][1], bB + ARRB);
            ldsm4(bl[2][0], bl[2][1], bl[3][0], bl[3][1], bB + ARRB + 16 * ROWH * 2);

#pragma unroll
            for (int mi = 0; mi < 4; mi++)
#pragma unroll
                for (int nj = 0; nj < 4; nj++)
                    mma16816(acc[mi][nj], ah[mi], bh[nj]);
#pragma unroll
            for (int mi = 0; mi < 4; mi++)
#pragma unroll
                for (int nj = 0; nj < 4; nj++)
                    mma16816(acc[mi][nj], ah[mi], bl[nj]);
#pragma unroll
            for (int mi = 0; mi < 4; mi++)
#pragma unroll
                for (int nj = 0; nj < 4; nj++)
                    mma16816(acc[mi][nj], al[mi], bh[nj]);
        }
        __syncthreads();
        if (s + 2 < NSTAGE) load_stage(s + 2);
    }

#pragma unroll
    for (int mi = 0; mi < 4; mi++) {
        const int r0 = bm + wm * 64 + mi * 16 + g;
#pragma unroll
        for (int nj = 0; nj < 4; nj++) {
            const int c0 = bn + wn * 32 + nj * 8 + t2;
            const float b0 = bias[c0], b1 = bias[c0 + 1];
            float v00 = acc[mi][nj][0] + b0, v01 = acc[mi][nj][1] + b1;
            float v10 = acc[mi][nj][2] + b0, v11 = acc[mi][nj][3] + b1;
            if (CF) {
                *(float2*)&CF[(size_t)r0 * D_ + c0]       = make_float2(v00, v01);
                *(float2*)&CF[(size_t)(r0 + 8) * D_ + c0] = make_float2(v10, v11);
            } else {
                uint32_t h0, l0, h1, l1;
                split2(v00 * scale, v01 * scale, h0, l0);
                split2(v10 * scale, v11 * scale, h1, l1);
                *(uint32_t*)&CH[(size_t)r0 * D_ + c0]       = h0;
                *(uint32_t*)&CL[(size_t)r0 * D_ + c0]       = l0;
                *(uint32_t*)&CH[(size_t)(r0 + 8) * D_ + c0] = h1;
                *(uint32_t*)&CL[(size_t)(r0 + 8) * D_ + c0] = l1;
            }
        }
    }
}

// ---------------------------------------------------------------------------
// HMMA flash-attention v2: warp = 32 queries (2 m-tiles), CTA = 4 warps /
// 128 queries. K and V both loaded natural [key][dim] via cp.async; K
// B-frags via ldmatrix.x4, V B-frags via ldmatrix.x4.trans. Double buffer,
// one barrier per tile. bf16x3 on both GEMMs.
// ---------------------------------------------------------------------------
#define AT_ARR   4608                   // 64*72 halves per array
#define AT_SMEM  (8 * AT_ARR * 2)       // 73728 bytes: 2 buf x {Kh,Kl,Vh,Vl}
#define NTILE_   (S_ / 64)              // 32

__global__ __launch_bounds__(128, 2)
void attn_hmma(const __nv_bfloat16* __restrict__ qH, const __nv_bfloat16* __restrict__ qL,
               const __nv_bfloat16* __restrict__ kH, const __nv_bfloat16* __restrict__ kL,
               const __nv_bfloat16* __restrict__ vH, const __nv_bfloat16* __restrict__ vL,
               __nv_bfloat16* __restrict__ yH, __nv_bfloat16* __restrict__ yL)
{
    extern __shared__ __align__(16) uint16_t sm[];
    const int tid  = threadIdx.x;
    const int wid  = tid >> 5;          // 0..3
    const int lane = tid & 31;
    const int g    = lane >> 2;
    const int t2   = (lane & 3) * 2;
    const int q0   = blockIdx.x * 128;
    const int bh   = blockIdx.y;
    const int b    = bh >> 4;
    const int h    = bh & 15;
    const int col0 = h * HD_;
    const int m0   = b * S_ + q0 + wid * 32;   // warp's first query row

    // ldmatrix address lane components
    const int krow = (lane & 7) + 8 * ((lane >> 4) & 1);  // K: row sel
    const int kc16 = 16 * ((lane >> 3) & 1);              // K: k-byte sel
    const int vrow = (lane & 7) + 8 * ((lane >> 3) & 1);  // V: key-row sel
    const int vc16 = 16 * ((lane >> 4) & 1);              // V: dim-byte sel

    // ---- Q fragments: 2 m-tiles x 4 k-chunks x hi/lo ----
    uint32_t qh[2][4][4], ql[2][4][4];
#pragma unroll
    for (int mi = 0; mi < 2; mi++) {
        const int r0 = m0 + mi * 16;
        const __nv_bfloat16* p0h = qH + (size_t)(r0 + g) * D_ + col0;
        const __nv_bfloat16* p1h = qH + (size_t)(r0 + g + 8) * D_ + col0;
        const __nv_bfloat16* p0l = qL + (size_t)(r0 + g) * D_ + col0;
        const __nv_bfloat16* p1l = qL + (size_t)(r0 + g + 8) * D_ + col0;
#pragma unroll
        for (int kc = 0; kc < 4; kc++) {
            qh[mi][kc][0] = *(const uint32_t*)(p0h + kc * 16 + t2);
            qh[mi][kc][1] = *(const uint32_t*)(p1h + kc * 16 + t2);
            qh[mi][kc][2] = *(const uint32_t*)(p0h + kc * 16 + t2 + 8);
            qh[mi][kc][3] = *(const uint32_t*)(p1h + kc * 16 + t2 + 8);
            ql[mi][kc][0] = *(const uint32_t*)(p0l + kc * 16 + t2);
            ql[mi][kc][1] = *(const uint32_t*)(p1l + kc * 16 + t2);
            ql[mi][kc][2] = *(const uint32_t*)(p0l + kc * 16 + t2 + 8);
            ql[mi][kc][3] = *(const uint32_t*)(p1l + kc * 16 + t2 + 8);
        }
    }

    const uint32_t smb = smem_u32(sm);
    const __nv_bfloat16* gsrc[4] = {kH, kL, vH, vL};

    // 2048 16B chunks / 128 threads = 16 per thread
    auto load_tile = [&](int kb, int buf) {
#pragma unroll
        for (int i = 0; i < 16; i++) {
            int c = i * 128 + tid;
            int a = c >> 9;              // array 0..3
            int idx = c & 511;
            int row = idx >> 3, qq = idx & 7;
            uint32_t dst = smb + ((buf * 4 + a) * AT_ARR + row * 72 + qq * 8) * 2;
            const __nv_bfloat16* src = gsrc[a]
                + (size_t)(b * S_ + kb + row) * D_ + col0 + qq * 8;
            cp_async16(dst, src);
        }
        cp_commit();
    };

    float of[2][8][4];
#pragma unroll
    for (int mi = 0; mi < 2; mi++)
#pragma unroll
        for (int j = 0; j < 8; j++)
#pragma unroll
            for (int r = 0; r < 4; r++) of[mi][j][r] = 0.0f;
    float mr[4] = {-1e30f, -1e30f, -1e30f, -1e30f};   // [mi*2 + rowhalf]
    float lr[4] = {0.0f, 0.0f, 0.0f, 0.0f};

    load_tile(0, 0);

    for (int it = 0; it < NTILE_; it++) {
        const int buf = it & 1;
        cp_wait0();
        __syncthreads();
        if (it + 1 < NTILE_) load_tile((it + 1) * 64, buf ^ 1);

        const uint32_t Khb = smb + (buf * 4 + 0) * AT_ARR * 2;
        const uint32_t Klb = smb + (buf * 4 + 1) * AT_ARR * 2;
        const uint32_t Vhb = smb + (buf * 4 + 2) * AT_ARR * 2;
        const uint32_t Vlb = smb + (buf * 4 + 3) * AT_ARR * 2;

        // ---- S = Q K^T ----
        float sf[2][8][4];
#pragma unroll
        for (int mi = 0; mi < 2; mi++)
#pragma unroll
            for (int j = 0; j < 8; j++)
#pragma unroll
                for (int r = 0; r < 4; r++) sf[mi][j][r] = 0.0f;

#pragma unroll
        for (int kc = 0; kc < 4; kc++) {
#pragma unroll
            for (int jp = 0; jp < 4; jp++) {
                uint32_t kh4[4], kl4[4];
                const uint32_t off = (jp * 16 + krow) * 144 + kc * 32 + kc16;
                ldsm4(kh4[0], kh4[1], kh4[2], kh4[3], Khb + off);
                ldsm4(kl4[0], kl4[1], kl4[2], kl4[3], Klb + off);
                // term 1: qh * Kh
#pragma unroll
                for (int mi = 0; mi < 2; mi++) {
                    mma16816(sf[mi][2*jp],   qh[mi][kc], &kh4[0]);
                    mma16816(sf[mi][2*jp+1], qh[mi][kc], &kh4[2]);
                }
                // term 2: qh * Kl
#pragma unroll
                for (int mi = 0; mi < 2; mi++) {
                    mma16816(sf[mi][2*jp],   qh[mi][kc], &kl4[0]);
                    mma16816(sf[mi][2*jp+1], qh[mi][kc], &kl4[2]);
                }
                // term 3: ql * Kh
#pragma unroll
                for (int mi = 0; mi < 2; mi++) {
                    mma16816(sf[mi][2*jp],   ql[mi][kc], &kh4[0]);
                    mma16816(sf[mi][2*jp+1], ql[mi][kc], &kh4[2]);
                }
            }
        }

        // ---- online softmax (per m-tile; quad reductions) ----
#pragma unroll
        for (int mi = 0; mi < 2; mi++) {
            float tm0 = -1e30f, tm1 = -1e30f;
#pragma unroll
            for (int j = 0; j < 8; j++) {
                tm0 = fmaxf(tm0, fmaxf(sf[mi][j][0], sf[mi][j][1]));
                tm1 = fmaxf(tm1, fmaxf(sf[mi][j][2], sf[mi][j][3]));
            }
            tm0 = fmaxf(tm0, __shfl_xor_sync(0xffffffffu, tm0, 1));
            tm0 = fmaxf(tm0, __shfl_xor_sync(0xffffffffu, tm0, 2));
            tm1 = fmaxf(tm1, __shfl_xor_sync(0xffffffffu, tm1, 1));
            tm1 = fmaxf(tm1, __shfl_xor_sync(0xffffffffu, tm1, 2));
            const float mn0 = fmaxf(mr[mi*2],   tm0);
            const float mn1 = fmaxf(mr[mi*2+1], tm1);
            const float al0 = __expf(mr[mi*2]   - mn0);
            const float al1 = __expf(mr[mi*2+1] - mn1);
            float rs0 = 0.0f, rs1 = 0.0f;
#pragma unroll
            for (int j = 0; j < 8; j++) {
                sf[mi][j][0] = __expf(sf[mi][j][0] - mn0);
                sf[mi][j][1] = __expf(sf[mi][j][1] - mn0);
                sf[mi][j][2] = __expf(sf[mi][j][2] - mn1);
                sf[mi][j][3] = __expf(sf[mi][j][3] - mn1);
                rs0 += sf[mi][j][0] + sf[mi][j][1];
                rs1 += sf[mi][j][2] + sf[mi][j][3];
            }
            rs0 += __shfl_xor_sync(0xffffffffu, rs0, 1);
            rs0 += __shfl_xor_sync(0xffffffffu, rs0, 2);
            rs1 += __shfl_xor_sync(0xffffffffu, rs1, 1);
            rs1 += __shfl_xor_sync(0xffffffffu, rs1, 2);
            lr[mi*2]   = lr[mi*2]   * al0 + rs0;
            lr[mi*2+1] = lr[mi*2+1] * al1 + rs1;
            mr[mi*2] = mn0; mr[mi*2+1] = mn1;
#pragma unroll
            for (int j = 0; j < 8; j++) {
                of[mi][j][0] *= al0; of[mi][j][1] *= al0;
                of[mi][j][2] *= al1; of[mi][j][3] *= al1;
            }
        }

        // ---- O += P V  (P split in registers; V frags via ldmatrix.trans) ----
#pragma unroll
        for (int kc = 0; kc < 4; kc++) {
            uint32_t pah[2][4], pal[2][4];
#pragma unroll
            for (int mi = 0; mi < 2; mi++) {
                split2(sf[mi][2*kc][0],   sf[mi][2*kc][1],   pah[mi][0], pal[mi][0]);
                split2(sf[mi][2*kc][2],   sf[mi][2*kc][3],   pah[mi][1], pal[mi][1]);
                split2(sf[mi][2*kc+1][0], sf[mi][2*kc+1][1], pah[mi][2], pal[mi][2]);
                split2(sf[mi][2*kc+1][2], sf[mi][2*kc+1][3], pah[mi][3], pal[mi][3]);
            }
#pragma unroll
            for (int dp = 0; dp < 4; dp++) {
                uint32_t vh4[4], vl4[4];
                const uint32_t off = (kc * 16 + vrow) * 144 + dp * 32 + vc16;
                ldsm4t(vh4[0], vh4[1], vh4[2], vh4[3], Vhb + off);
                ldsm4t(vl4[0], vl4[1], vl4[2], vl4[3], Vlb + off);
#pragma unroll
                for (int mi = 0; mi < 2; mi++) {
                    mma16816(of[mi][2*dp],   pah[mi], &vh4[0]);
                    mma16816(of[mi][2*dp+1], pah[mi], &vh4[2]);
                }
#pragma unroll
                for (int mi = 0; mi < 2; mi++) {
                    mma16816(of[mi][2*dp],   pah[mi], &vl4[0]);
                    mma16816(of[mi][2*dp+1], pah[mi], &vl4[2]);
                }
#pragma unroll
                for (int mi = 0; mi < 2; mi++) {
                    mma16816(of[mi][2*dp],   pal[mi], &vh4[0]);
                    mma16816(of[mi][2*dp+1], pal[mi], &vh4[2]);
                }
            }
        }
    }

    // ---- epilogue: normalize, split, store Y ----
#pragma unroll
    for (int mi = 0; mi < 2; mi++) {
        const float inv0 = 1.0f / lr[mi*2];
        const float inv1 = 1.0f / lr[mi*2+1];
        const int r0 = m0 + mi * 16;
#pragma unroll
        for (int j = 0; j < 8; j++) {
            uint32_t h0, l0, h1, l1;
            split2(of[mi][j][0] * inv0, of[mi][j][1] * inv0, h0, l0);
            split2(of[mi][j][2] * inv1, of[mi][j][3] * inv1, h1, l1);
            const size_t o0 = (size_t)(r0 + g) * D_ + col0 + j * 8 + t2;
            const size_t o1 = (size_t)(r0 + g + 8) * D_ + col0 + j * 8 + t2;
            *(uint32_t*)&yH[o0] = h0;
            *(uint32_t*)&yL[o0] = l0;
            *(uint32_t*)&yH[o1] = h1;
            *(uint32_t*)&yL[o1] = l1;
        }
    }
}

// ---------------------------------------------------------------------------
// Launch. ncu -s 5 -c 1 captures the 6th launch = attn_hmma.
// ---------------------------------------------------------------------------
extern "C" void kernel_launch(void* const* d_in, const int* in_sizes, int n_in,
                              void* d_out, int out_size)
{
    const float* dec = (const float*)d_in[0];
    const float* enc = (const float*)d_in[1];
    const float* Wq  = (const float*)d_in[2];
    const float* bq  = (const float*)d_in[3];
    const float* Wk  = (const float*)d_in[4];
    const float* bk  = (const float*)d_in[5];
    const float* Wv  = (const float*)d_in[6];
    const float* bv  = (const float*)d_in[7];
    const float* Wp  = (const float*)d_in[8];
    const float* bp  = (const float*)d_in[9];
    float* out = (float*)d_out;

    __nv_bfloat16 *decH,*decL,*encH,*encL;
    __nv_bfloat16 *qHp,*qLp,*kHp,*kLp,*vHp,*vLp,*yHp,*yLp;
    __nv_bfloat16 *wqH,*wqL,*wkH,*wkL,*wvH,*wvL,*wpH,*wpL;
    cudaGetSymbolAddress((void**)&decH, g_decH); cudaGetSymbolAddress((void**)&decL, g_decL);
    cudaGetSymbolAddress((void**)&encH, g_encH); cudaGetSymbolAddress((void**)&encL, g_encL);
    cudaGetSymbolAddress((void**)&qHp, g_qH);   cudaGetSymbolAddress((void**)&qLp, g_qL);
    cudaGetSymbolAddress((void**)&kHp, g_kH);   cudaGetSymbolAddress((void**)&kLp, g_kL);
    cudaGetSymbolAddress((void**)&vHp, g_vH);   cudaGetSymbolAddress((void**)&vLp, g_vL);
    cudaGetSymbolAddress((void**)&yHp, g_yH);   cudaGetSymbolAddress((void**)&yLp, g_yL);
    cudaGetSymbolAddress((void**)&wqH, g_wqH);  cudaGetSymbolAddress((void**)&wqL, g_wqL);
    cudaGetSymbolAddress((void**)&wkH, g_wkH);  cudaGetSymbolAddress((void**)&wkL, g_wkL);
    cudaGetSymbolAddress((void**)&wvH, g_wvH);  cudaGetSymbolAddress((void**)&wvL, g_wvL);
    cudaGetSymbolAddress((void**)&wpH, g_wpH);  cudaGetSymbolAddress((void**)&wpL, g_wpL);

    cudaFuncSetAttribute(gemm_hmma3, cudaFuncAttributeMaxDynamicSharedMemorySize, GSMEM);
    cudaFuncSetAttribute(attn_hmma,  cudaFuncAttributeMaxDynamicSharedMemorySize, AT_SMEM);

    // 1: both activation splits; 2: all weight splits
    split_act2<<<(2 * NACT4_ + 255) / 256, 256>>>(dec, enc, decH, decL, encH, encL);
    split_w4<<<(4 * NW4_ + 255) / 256, 256>>>(Wq, Wk, Wv, Wp,
                                              wqH, wqL, wkH, wkL,
                                              wvH, wvL, wpH, wpL);

    dim3 ggrid(D_ / 128, M_ / 128);
    // 3,4,5: projections
    gemm_hmma3<<<ggrid, 256, GSMEM>>>(decH, decL, wqH, wqL, bq,
                                      nullptr, qHp, qLp, 0.125f);
    gemm_hmma3<<<ggrid, 256, GSMEM>>>(encH, encL, wkH, wkL, bk,
                                      nullptr, kHp, kLp, 1.0f);
    gemm_hmma3<<<ggrid, 256, GSMEM>>>(encH, encL, wvH, wvL, bv,
                                      nullptr, vHp, vLp, 1.0f);

    // 6: attention (ncu capture target)
    attn_hmma<<<dim3(S_ / 128, B_ * H_), 128, AT_SMEM>>>(qHp, qLp, kHp, kLp,
                                                         vHp, vLp, yHp, yLp);

    // 7: output projection
    gemm_hmma3<<<ggrid, 256, GSMEM>>>(yHp, yLp, wpH, wpL, bp,
                                      out, nullptr, nullptr, 1.0f);
}

// round 12
// speedup vs baseline: 3.7239x; 1.0191x over previous
#include <cuda_runtime.h>
#include <cuda_bf16.h>
#include <cstdint>

#define B_  2
#define S_  2048
#define D_  1024
#define H_  16
#define HD_ 64
#define M_  (B_*S_)   // 4096

// ---------------------------------------------------------------------------
// Scratch (device globals). All split bf16 pairs.
// ---------------------------------------------------------------------------
__device__ __nv_bfloat16 g_decH[M_*D_], g_decL[M_*D_];
__device__ __nv_bfloat16 g_encH[M_*D_], g_encL[M_*D_];
__device__ __nv_bfloat16 g_qH[M_*D_],   g_qL[M_*D_];
__device__ __nv_bfloat16 g_kH[M_*D_],   g_kL[M_*D_];
__device__ __nv_bfloat16 g_vH[M_*D_],   g_vL[M_*D_];
__device__ __nv_bfloat16 g_yH[M_*D_],   g_yL[M_*D_];
__device__ __nv_bfloat16 g_wqH[D_*D_],  g_wqL[D_*D_];
__device__ __nv_bfloat16 g_wkH[D_*D_],  g_wkL[D_*D_];
__device__ __nv_bfloat16 g_wvH[D_*D_],  g_wvL[D_*D_];
__device__ __nv_bfloat16 g_wpH[D_*D_],  g_wpL[D_*D_];

// ---------------------------------------------------------------------------
// fp32 -> (hi, lo) bf16 splits
// ---------------------------------------------------------------------------
__device__ __forceinline__ void split4_store(const float4 v,
                                             __nv_bfloat16* hi, __nv_bfloat16* lo, int i)
{
    float x[4] = {v.x, v.y, v.z, v.w};
    unsigned short h[4], l[4];
#pragma unroll
    for (int j = 0; j < 4; j++) {
        __nv_bfloat16 hb = __float2bfloat16(x[j]);
        __nv_bfloat16 lb = __float2bfloat16(x[j] - __bfloat162float(hb));
        h[j] = __bfloat16_as_ushort(hb);
        l[j] = __bfloat16_as_ushort(lb);
    }
    uint2 hv, lv;
    hv.x = (uint32_t)h[0] | ((uint32_t)h[1] << 16);
    hv.y = (uint32_t)h[2] | ((uint32_t)h[3] << 16);
    lv.x = (uint32_t)l[0] | ((uint32_t)l[1] << 16);
    lv.y = (uint32_t)l[2] | ((uint32_t)l[3] << 16);
    ((uint2*)hi)[i] = hv;
    ((uint2*)lo)[i] = lv;
}

#define NACT4_ (M_*D_/4)
__global__ __launch_bounds__(256)
void split_act2(const float* __restrict__ A0, const float* __restrict__ A1,
                __nv_bfloat16* __restrict__ H0, __nv_bfloat16* __restrict__ L0,
                __nv_bfloat16* __restrict__ H1, __nv_bfloat16* __restrict__ L1)
{
    int i = blockIdx.x * blockDim.x + threadIdx.x;
    int which = i >> 20;
    int idx   = i & (NACT4_ - 1);
    if (which == 0) split4_store(((const float4*)A0)[idx], H0, L0, idx);
    else            split4_store(((const float4*)A1)[idx], H1, L1, idx);
}

#define NW4_ (D_*D_/4)
__global__ __launch_bounds__(256)
void split_w4(const float* __restrict__ W0, const float* __restrict__ W1,
              const float* __restrict__ W2, const float* __restrict__ W3,
              __nv_bfloat16* __restrict__ H0, __nv_bfloat16* __restrict__ L0,
              __nv_bfloat16* __restrict__ H1, __nv_bfloat16* __restrict__ L1,
              __nv_bfloat16* __restrict__ H2, __nv_bfloat16* __restrict__ L2,
              __nv_bfloat16* __restrict__ H3, __nv_bfloat16* __restrict__ L3)
{
    int i = blockIdx.x * blockDim.x + threadIdx.x;
    int which = i >> 18;
    int idx   = i & (NW4_ - 1);
    const float* src; __nv_bfloat16 *hi, *lo;
    switch (which) {
        case 0:  src = W0; hi = H0; lo = L0; break;
        case 1:  src = W1; hi = H1; lo = L1; break;
        case 2:  src = W2; hi = H2; lo = L2; break;
        default: src = W3; hi = H3; lo = L3; break;
    }
    split4_store(((const float4*)src)[idx], hi, lo, idx);
}

// ---------------------------------------------------------------------------
// Helpers (baseline PTX only)
// ---------------------------------------------------------------------------
__device__ __forceinline__ uint32_t smem_u32(const void* p) {
    uint32_t a;
    asm("{ .reg .u64 t; cvta.to.shared.u64 t, %1; cvt.u32.u64 %0, t; }"
        : "=r"(a) : "l"(p));
    return a;
}

__device__ __forceinline__ void mma16816(float* c, const uint32_t* a, const uint32_t* b) {
    asm volatile(
        "mma.sync.aligned.m16n8k16.row.col.f32.bf16.bf16.f32 "
        "{%0,%1,%2,%3}, {%4,%5,%6,%7}, {%8,%9}, {%0,%1,%2,%3};"
        : "+f"(c[0]), "+f"(c[1]), "+f"(c[2]), "+f"(c[3])
        : "r"(a[0]), "r"(a[1]), "r"(a[2]), "r"(a[3]), "r"(b[0]), "r"(b[1]));
}

__device__ __forceinline__ void ldsm4(uint32_t& r0, uint32_t& r1,
                                      uint32_t& r2, uint32_t& r3, uint32_t addr) {
    asm volatile("ldmatrix.sync.aligned.m8n8.x4.shared.b16 {%0,%1,%2,%3}, [%4];"
                 : "=r"(r0), "=r"(r1), "=r"(r2), "=r"(r3) : "r"(addr));
}
__device__ __forceinline__ void ldsm4t(uint32_t& r0, uint32_t& r1,
                                       uint32_t& r2, uint32_t& r3, uint32_t addr) {
    asm volatile("ldmatrix.sync.aligned.m8n8.x4.trans.shared.b16 {%0,%1,%2,%3}, [%4];"
                 : "=r"(r0), "=r"(r1), "=r"(r2), "=r"(r3) : "r"(addr));
}

__device__ __forceinline__ void cp_async16(uint32_t dst, const void* src) {
    asm volatile("cp.async.cg.shared.global [%0], [%1], 16;\n"
                 :: "r"(dst), "l"(src) : "memory");
}
__device__ __forceinline__ void cp_commit() {
    asm volatile("cp.async.commit_group;\n" ::: "memory");
}
__device__ __forceinline__ void cp_wait1() {
    asm volatile("cp.async.wait_group 1;\n" ::: "memory");
}
__device__ __forceinline__ void cp_wait0() {
    asm volatile("cp.async.wait_group 0;\n" ::: "memory");
}

__device__ __forceinline__ void split2(float x, float y, uint32_t& hi, uint32_t& lo) {
    __nv_bfloat16 xh = __float2bfloat16(x);
    __nv_bfloat16 yh = __float2bfloat16(y);
    __nv_bfloat16 xl = __float2bfloat16(x - __bfloat162float(xh));
    __nv_bfloat16 yl = __float2bfloat16(y - __bfloat162float(yh));
    __nv_bfloat162 hv; hv.x = xh; hv.y = yh;
    __nv_bfloat162 lv; lv.x = xl; lv.y = yl;
    hi = *(uint32_t*)&hv; lo = *(uint32_t*)&lv;
}

// ---------------------------------------------------------------------------
// bf16x3 split GEMM v2: CTA 128x128, 4 warps of 64x64 (crossbar bytes/MMA
// 128 -> 85). B-frags streamed per 16-col pair; A hi/lo held per k-step.
// ---------------------------------------------------------------------------
#define KSTEP    32
#define NSTAGE   (D_ / KSTEP)
#define ROWH     40
#define ARRB     (128 * ROWH * 2)
#define STAGEB   (4 * ARRB)
#define GSMEM    (2 * STAGEB)

__global__ __launch_bounds__(128, 2)
void gemm_hmma3(const __nv_bfloat16* __restrict__ Ah, const __nv_bfloat16* __restrict__ Al,
                const __nv_bfloat16* __restrict__ Wh, const __nv_bfloat16* __restrict__ Wl,
                const float* __restrict__ bias,
                float* __restrict__ CF,
                __nv_bfloat16* __restrict__ CH, __nv_bfloat16* __restrict__ CL,
                float scale)
{
    extern __shared__ __align__(16) uint16_t sm[];

    const int tid  = threadIdx.x;
    const int wid  = tid >> 5;       // 0..3
    const int lane = tid & 31;
    const int g    = lane >> 2;
    const int t2   = (lane & 3) * 2;
    const int wm   = wid >> 1;       // 0..1
    const int wn   = wid & 1;        // 0..1
    const int bn   = blockIdx.x * 128;
    const int bm   = blockIdx.y * 128;

    const int lr   = lane & 7;
    const int lrow = lr + 8 * ((lane >> 3) & 1);   // A row sel
    const int lkh  = 8 * ((lane >> 4) & 1);        // A k sel
    const int brow = lr + 8 * ((lane >> 4) & 1);   // B row sel
    const int bk   = 8 * ((lane >> 3) & 1);        // B k sel

    const uint32_t smb = smem_u32(sm);

    // 2048 16B chunks / 128 threads = 16 per thread; arr = i>>2 (compile-time)
    auto load_stage = [&](int s) {
        const int buf = s & 1;
        const int k0  = s * KSTEP;
        const uint32_t base = smb + buf * STAGEB;
#pragma unroll
        for (int i = 0; i < 16; i++) {
            const int c   = i * 128 + tid;
            const int arr = i >> 2;              // constant per unrolled i
            const int idx = c & 511;
            const int row = idx >> 2;
            const int q   = idx & 3;
            const __nv_bfloat16* gp = (arr == 0) ? Ah : (arr == 1) ? Al
                                    : (arr == 2) ? Wh : Wl;
            const int r0 = (arr < 2) ? bm : bn;
            cp_async16(base + arr * ARRB + row * (ROWH * 2) + q * 16,
                       gp + (size_t)(r0 + row) * D_ + k0 + q * 8);
        }
        cp_commit();
    };

    float acc[4][8][4];
#pragma unroll
    for (int mi = 0; mi < 4; mi++)
#pragma unroll
        for (int nj = 0; nj < 8; nj++)
#pragma unroll
            for (int r = 0; r < 4; r++) acc[mi][nj][r] = 0.0f;

    load_stage(0);
    load_stage(1);

    for (int s = 0; s < NSTAGE; s++) {
        const int buf = s & 1;
        if (s < NSTAGE - 1) cp_wait1(); else cp_wait0();
        __syncthreads();

        const uint32_t sb = smb + buf * STAGEB;

#pragma unroll
        for (int ks = 0; ks < 2; ks++) {
            const int ko = ks * 16;
            uint32_t ah[4][4], al[4][4];

            const uint32_t aA = sb + ((wm * 64 + lrow) * ROWH + ko + lkh) * 2;
#pragma unroll
            for (int mi = 0; mi < 4; mi++)
                ldsm4(ah[mi][0], ah[mi][1], ah[mi][2], ah[mi][3],
                      aA + mi * (16 * ROWH * 2));
#pragma unroll
            for (int mi = 0; mi < 4; mi++)
                ldsm4(al[mi][0], al[mi][1], al[mi][2], al[mi][3],
                      aA + ARRB + mi * (16 * ROWH * 2));

            const uint32_t bB = sb + 2 * ARRB
                              + ((wn * 64 + brow) * ROWH + ko + bk) * 2;
#pragma unroll
            for (int jp = 0; jp < 4; jp++) {
                uint32_t bh4[4], bl4[4];
                ldsm4(bh4[0], bh4[1], bh4[2], bh4[3],
                      bB + jp * (16 * ROWH * 2));
                ldsm4(bl4[0], bl4[1], bl4[2], bl4[3],
                      bB + ARRB + jp * (16 * ROWH * 2));
                // term 1: Ah * Wh
#pragma unroll
                for (int mi = 0; mi < 4; mi++) {
                    mma16816(acc[mi][2*jp],   ah[mi], &bh4[0]);
                    mma16816(acc[mi][2*jp+1], ah[mi], &bh4[2]);
                }
                // term 2: Ah * Wl
#pragma unroll
                for (int mi = 0; mi < 4; mi++) {
                    mma16816(acc[mi][2*jp],   ah[mi], &bl4[0]);
                    mma16816(acc[mi][2*jp+1], ah[mi], &bl4[2]);
                }
                // term 3: Al * Wh
#pragma unroll
                for (int mi = 0; mi < 4; mi++) {
                    mma16816(acc[mi][2*jp],   al[mi], &bh4[0]);
                    mma16816(acc[mi][2*jp+1], al[mi], &bh4[2]);
                }
            }
        }
        __syncthreads();
        if (s + 2 < NSTAGE) load_stage(s + 2);
    }

    // ---- epilogue ----
#pragma unroll
    for (int mi = 0; mi < 4; mi++) {
        const int r0 = bm + wm * 64 + mi * 16 + g;
#pragma unroll
        for (int nj = 0; nj < 8; nj++) {
            const int c0 = bn + wn * 64 + nj * 8 + t2;
            const float b0 = bias[c0], b1 = bias[c0 + 1];
            float v00 = acc[mi][nj][0] + b0, v01 = acc[mi][nj][1] + b1;
            float v10 = acc[mi][nj][2] + b0, v11 = acc[mi][nj][3] + b1;
            if (CF) {
                *(float2*)&CF[(size_t)r0 * D_ + c0]       = make_float2(v00, v01);
                *(float2*)&CF[(size_t)(r0 + 8) * D_ + c0] = make_float2(v10, v11);
            } else {
                uint32_t h0, l0, h1, l1;
                split2(v00 * scale, v01 * scale, h0, l0);
                split2(v10 * scale, v11 * scale, h1, l1);
                *(uint32_t*)&CH[(size_t)r0 * D_ + c0]       = h0;
                *(uint32_t*)&CL[(size_t)r0 * D_ + c0]       = l0;
                *(uint32_t*)&CH[(size_t)(r0 + 8) * D_ + c0] = h1;
                *(uint32_t*)&CL[(size_t)(r0 + 8) * D_ + c0] = l1;
            }
        }
    }
}

// ---------------------------------------------------------------------------
// HMMA flash-attention v2 (unchanged from round 8 — validated at ~250us).
// ---------------------------------------------------------------------------
#define AT_ARR   4608
#define AT_SMEM  (8 * AT_ARR * 2)
#define NTILE_   (S_ / 64)

__global__ __launch_bounds__(128, 2)
void attn_hmma(const __nv_bfloat16* __restrict__ qH, const __nv_bfloat16* __restrict__ qL,
               const __nv_bfloat16* __restrict__ kH, const __nv_bfloat16* __restrict__ kL,
               const __nv_bfloat16* __restrict__ vH, const __nv_bfloat16* __restrict__ vL,
               __nv_bfloat16* __restrict__ yH, __nv_bfloat16* __restrict__ yL)
{
    extern __shared__ __align__(16) uint16_t sm[];
    const int tid  = threadIdx.x;
    const int wid  = tid >> 5;
    const int lane = tid & 31;
    const int g    = lane >> 2;
    const int t2   = (lane & 3) * 2;
    const int q0   = blockIdx.x * 128;
    const int bh   = blockIdx.y;
    const int b    = bh >> 4;
    const int h    = bh & 15;
    const int col0 = h * HD_;
    const int m0   = b * S_ + q0 + wid * 32;

    const int krow = (lane & 7) + 8 * ((lane >> 4) & 1);
    const int kc16 = 16 * ((lane >> 3) & 1);
    const int vrow = (lane & 7) + 8 * ((lane >> 3) & 1);
    const int vc16 = 16 * ((lane >> 4) & 1);

    uint32_t qh[2][4][4], ql[2][4][4];
#pragma unroll
    for (int mi = 0; mi < 2; mi++) {
        const int r0 = m0 + mi * 16;
        const __nv_bfloat16* p0h = qH + (size_t)(r0 + g) * D_ + col0;
        const __nv_bfloat16* p1h = qH + (size_t)(r0 + g + 8) * D_ + col0;
        const __nv_bfloat16* p0l = qL + (size_t)(r0 + g) * D_ + col0;
        const __nv_bfloat16* p1l = qL + (size_t)(r0 + g + 8) * D_ + col0;
#pragma unroll
        for (int kc = 0; kc < 4; kc++) {
            qh[mi][kc][0] = *(const uint32_t*)(p0h + kc * 16 + t2);
            qh[mi][kc][1] = *(const uint32_t*)(p1h + kc * 16 + t2);
            qh[mi][kc][2] = *(const uint32_t*)(p0h + kc * 16 + t2 + 8);
            qh[mi][kc][3] = *(const uint32_t*)(p1h + kc * 16 + t2 + 8);
            ql[mi][kc][0] = *(const uint32_t*)(p0l + kc * 16 + t2);
            ql[mi][kc][1] = *(const uint32_t*)(p1l + kc * 16 + t2);
            ql[mi][kc][2] = *(const uint32_t*)(p0l + kc * 16 + t2 + 8);
            ql[mi][kc][3] = *(const uint32_t*)(p1l + kc * 16 + t2 + 8);
        }
    }

    const uint32_t smb = smem_u32(sm);
    const __nv_bfloat16* gsrc[4] = {kH, kL, vH, vL};

    auto load_tile = [&](int kb, int buf) {
#pragma unroll
        for (int i = 0; i < 16; i++) {
            int c = i * 128 + tid;
            int a = c >> 9;
            int idx = c & 511;
            int row = idx >> 3, qq = idx & 7;
            uint32_t dst = smb + ((buf * 4 + a) * AT_ARR + row * 72 + qq * 8) * 2;
            const __nv_bfloat16* src = gsrc[a]
                + (size_t)(b * S_ + kb + row) * D_ + col0 + qq * 8;
            cp_async16(dst, src);
        }
        cp_commit();
    };

    float of[2][8][4];
#pragma unroll
    for (int mi = 0; mi < 2; mi++)
#pragma unroll
        for (int j = 0; j < 8; j++)
#pragma unroll
            for (int r = 0; r < 4; r++) of[mi][j][r] = 0.0f;
    float mr[4] = {-1e30f, -1e30f, -1e30f, -1e30f};
    float lr[4] = {0.0f, 0.0f, 0.0f, 0.0f};

    load_tile(0, 0);

    for (int it = 0; it < NTILE_; it++) {
        const int buf = it & 1;
        cp_wait0();
        __syncthreads();
        if (it + 1 < NTILE_) load_tile((it + 1) * 64, buf ^ 1);

        const uint32_t Khb = smb + (buf * 4 + 0) * AT_ARR * 2;
        const uint32_t Klb = smb + (buf * 4 + 1) * AT_ARR * 2;
        const uint32_t Vhb = smb + (buf * 4 + 2) * AT_ARR * 2;
        const uint32_t Vlb = smb + (buf * 4 + 3) * AT_ARR * 2;

        float sf[2][8][4];
#pragma unroll
        for (int mi = 0; mi < 2; mi++)
#pragma unroll
            for (int j = 0; j < 8; j++)
#pragma unroll
                for (int r = 0; r < 4; r++) sf[mi][j][r] = 0.0f;

#pragma unroll
        for (int kc = 0; kc < 4; kc++) {
#pragma unroll
            for (int jp = 0; jp < 4; jp++) {
                uint32_t kh4[4], kl4[4];
                const uint32_t off = (jp * 16 + krow) * 144 + kc * 32 + kc16;
                ldsm4(kh4[0], kh4[1], kh4[2], kh4[3], Khb + off);
                ldsm4(kl4[0], kl4[1], kl4[2], kl4[3], Klb + off);
#pragma unroll
                for (int mi = 0; mi < 2; mi++) {
                    mma16816(sf[mi][2*jp],   qh[mi][kc], &kh4[0]);
                    mma16816(sf[mi][2*jp+1], qh[mi][kc], &kh4[2]);
                }
#pragma unroll
                for (int mi = 0; mi < 2; mi++) {
                    mma16816(sf[mi][2*jp],   qh[mi][kc], &kl4[0]);
                    mma16816(sf[mi][2*jp+1], qh[mi][kc], &kl4[2]);
                }
#pragma unroll
                for (int mi = 0; mi < 2; mi++) {
                    mma16816(sf[mi][2*jp],   ql[mi][kc], &kh4[0]);
                    mma16816(sf[mi][2*jp+1], ql[mi][kc], &kh4[2]);
                }
            }
        }

#pragma unroll
        for (int mi = 0; mi < 2; mi++) {
            float tm0 = -1e30f, tm1 = -1e30f;
#pragma unroll
            for (int j = 0; j < 8; j++) {
                tm0 = fmaxf(tm0, fmaxf(sf[mi][j][0], sf[mi][j][1]));
                tm1 = fmaxf(tm1, fmaxf(sf[mi][j][2], sf[mi][j][3]));
            }
            tm0 = fmaxf(tm0, __shfl_xor_sync(0xffffffffu, tm0, 1));
            tm0 = fmaxf(tm0, __shfl_xor_sync(0xffffffffu, tm0, 2));
            tm1 = fmaxf(tm1, __shfl_xor_sync(0xffffffffu, tm1, 1));
            tm1 = fmaxf(tm1, __shfl_xor_sync(0xffffffffu, tm1, 2));
            const float mn0 = fmaxf(mr[mi*2],   tm0);
            const float mn1 = fmaxf(mr[mi*2+1], tm1);
            const float al0 = __expf(mr[mi*2]   - mn0);
            const float al1 = __expf(mr[mi*2+1] - mn1);
            float rs0 = 0.0f, rs1 = 0.0f;
#pragma unroll
            for (int j = 0; j < 8; j++) {
                sf[mi][j][0] = __expf(sf[mi][j][0] - mn0);
                sf[mi][j][1] = __expf(sf[mi][j][1] - mn0);
                sf[mi][j][2] = __expf(sf[mi][j][2] - mn1);
                sf[mi][j][3] = __expf(sf[mi][j][3] - mn1);
                rs0 += sf[mi][j][0] + sf[mi][j][1];
                rs1 += sf[mi][j][2] + sf[mi][j][3];
            }
            rs0 += __shfl_xor_sync(0xffffffffu, rs0, 1);
            rs0 += __shfl_xor_sync(0xffffffffu, rs0, 2);
            rs1 += __shfl_xor_sync(0xffffffffu, rs1, 1);
            rs1 += __shfl_xor_sync(0xffffffffu, rs1, 2);
            lr[mi*2]   = lr[mi*2]   * al0 + rs0;
            lr[mi*2+1] = lr[mi*2+1] * al1 + rs1;
            mr[mi*2] = mn0; mr[mi*2+1] = mn1;
#pragma unroll
            for (int j = 0; j < 8; j++) {
                of[mi][j][0] *= al0; of[mi][j][1] *= al0;
                of[mi][j][2] *= al1; of[mi][j][3] *= al1;
            }
        }

#pragma unroll
        for (int kc = 0; kc < 4; kc++) {
            uint32_t pah[2][4], pal[2][4];
#pragma unroll
            for (int mi = 0; mi < 2; mi++) {
                split2(sf[mi][2*kc][0],   sf[mi][2*kc][1],   pah[mi][0], pal[mi][0]);
                split2(sf[mi][2*kc][2],   sf[mi][2*kc][3],   pah[mi][1], pal[mi][1]);
                split2(sf[mi][2*kc+1][0], sf[mi][2*kc+1][1], pah[mi][2], pal[mi][2]);
                split2(sf[mi][2*kc+1][2], sf[mi][2*kc+1][3], pah[mi][3], pal[mi][3]);
            }
#pragma unroll
            for (int dp = 0; dp < 4; dp++) {
                uint32_t vh4[4], vl4[4];
                const uint32_t off = (kc * 16 + vrow) * 144 + dp * 32 + vc16;
                ldsm4t(vh4[0], vh4[1], vh4[2], vh4[3], Vhb + off);
                ldsm4t(vl4[0], vl4[1], vl4[2], vl4[3], Vlb + off);
#pragma unroll
                for (int mi = 0; mi < 2; mi++) {
                    mma16816(of[mi][2*dp],   pah[mi], &vh4[0]);
                    mma16816(of[mi][2*dp+1], pah[mi], &vh4[2]);
                }
#pragma unroll
                for (int mi = 0; mi < 2; mi++) {
                    mma16816(of[mi][2*dp],   pah[mi], &vl4[0]);
                    mma16816(of[mi][2*dp+1], pah[mi], &vl4[2]);
                }
#pragma unroll
                for (int mi = 0; mi < 2; mi++) {
                    mma16816(of[mi][2*dp],   pal[mi], &vh4[0]);
                    mma16816(of[mi][2*dp+1], pal[mi], &vh4[2]);
                }
            }
        }
    }

#pragma unroll
    for (int mi = 0; mi < 2; mi++) {
        const float inv0 = 1.0f / lr[mi*2];
        const float inv1 = 1.0f / lr[mi*2+1];
        const int r0 = m0 + mi * 16;
#pragma unroll
        for (int j = 0; j < 8; j++) {
            uint32_t h0, l0, h1, l1;
            split2(of[mi][j][0] * inv0, of[mi][j][1] * inv0, h0, l0);
            split2(of[mi][j][2] * inv1, of[mi][j][3] * inv1, h1, l1);
            const size_t o0 = (size_t)(r0 + g) * D_ + col0 + j * 8 + t2;
            const size_t o1 = (size_t)(r0 + g + 8) * D_ + col0 + j * 8 + t2;
            *(uint32_t*)&yH[o0] = h0;
            *(uint32_t*)&yL[o0] = l0;
            *(uint32_t*)&yH[o1] = h1;
            *(uint32_t*)&yL[o1] = l1;
        }
    }
}

// ---------------------------------------------------------------------------
// Launch
// ---------------------------------------------------------------------------
extern "C" void kernel_launch(void* const* d_in, const int* in_sizes, int n_in,
                              void* d_out, int out_size)
{
    const float* dec = (const float*)d_in[0];
    const float* enc = (const float*)d_in[1];
    const float* Wq  = (const float*)d_in[2];
    const float* bq  = (const float*)d_in[3];
    const float* Wk  = (const float*)d_in[4];
    const float* bk  = (const float*)d_in[5];
    const float* Wv  = (const float*)d_in[6];
    const float* bv  = (const float*)d_in[7];
    const float* Wp  = (const float*)d_in[8];
    const float* bp  = (const float*)d_in[9];
    float* out = (float*)d_out;

    __nv_bfloat16 *decH,*decL,*encH,*encL;
    __nv_bfloat16 *qHp,*qLp,*kHp,*kLp,*vHp,*vLp,*yHp,*yLp;
    __nv_bfloat16 *wqH,*wqL,*wkH,*wkL,*wvH,*wvL,*wpH,*wpL;
    cudaGetSymbolAddress((void**)&decH, g_decH); cudaGetSymbolAddress((void**)&decL, g_decL);
    cudaGetSymbolAddress((void**)&encH, g_encH); cudaGetSymbolAddress((void**)&encL, g_encL);
    cudaGetSymbolAddress((void**)&qHp, g_qH);   cudaGetSymbolAddress((void**)&qLp, g_qL);
    cudaGetSymbolAddress((void**)&kHp, g_kH);   cudaGetSymbolAddress((void**)&kLp, g_kL);
    cudaGetSymbolAddress((void**)&vHp, g_vH);   cudaGetSymbolAddress((void**)&vLp, g_vL);
    cudaGetSymbolAddress((void**)&yHp, g_yH);   cudaGetSymbolAddress((void**)&yLp, g_yL);
    cudaGetSymbolAddress((void**)&wqH, g_wqH);  cudaGetSymbolAddress((void**)&wqL, g_wqL);
    cudaGetSymbolAddress((void**)&wkH, g_wkH);  cudaGetSymbolAddress((void**)&wkL, g_wkL);
    cudaGetSymbolAddress((void**)&wvH, g_wvH);  cudaGetSymbolAddress((void**)&wvL, g_wvL);
    cudaGetSymbolAddress((void**)&wpH, g_wpH);  cudaGetSymbolAddress((void**)&wpL, g_wpL);

    cudaFuncSetAttribute(gemm_hmma3, cudaFuncAttributeMaxDynamicSharedMemorySize, GSMEM);
    cudaFuncSetAttribute(attn_hmma,  cudaFuncAttributeMaxDynamicSharedMemorySize, AT_SMEM);

    split_act2<<<(2 * NACT4_ + 255) / 256, 256>>>(dec, enc, decH, decL, encH, encL);
    split_w4<<<(4 * NW4_ + 255) / 256, 256>>>(Wq, Wk, Wv, Wp,
                                              wqH, wqL, wkH, wkL,
                                              wvH, wvL, wpH, wpL);

    dim3 ggrid(D_ / 128, M_ / 128);
    gemm_hmma3<<<ggrid, 128, GSMEM>>>(decH, decL, wqH, wqL, bq,
                                      nullptr, qHp, qLp, 0.125f);
    gemm_hmma3<<<ggrid, 128, GSMEM>>>(encH, encL, wkH, wkL, bk,
                                      nullptr, kHp, kLp, 1.0f);
    gemm_hmma3<<<ggrid, 128, GSMEM>>>(encH, encL, wvH, wvL, bv,
                                      nullptr, vHp, vLp, 1.0f);

    attn_hmma<<<dim3(S_ / 128, B_ * H_), 128, AT_SMEM>>>(qHp, qLp, kHp, kLp,
                                                         vHp, vLp, yHp, yLp);

    gemm_hmma3<<<ggrid, 128, GSMEM>>>(yHp, yLp, wpH, wpL, bp,
                                      out, nullptr, nullptr, 1.0f);
}